// round 13
// baseline (speedup 1.0000x reference)
#include <cuda_runtime.h>
#include <cuda_fp16.h>
#include <cstdint>

#define BATCH 16384

// ---------------- static scratch (device globals; no allocations) ----------------
__device__ float g_bufA[(long long)BATCH * 6000];
__device__ float g_bufB[(long long)BATCH * 3000];
__device__ float g_bufC[(long long)BATCH * 1875];
__device__ float g_x1 [(long long)BATCH * 2250];
__device__ float g_x2 [(long long)BATCH * 3750];
// half (hi,lo) interleaved planes for tensor-core consumers
__device__ __half2 g_hX[(long long)BATCH * 3750];
__device__ __half2 g_hB[(long long)BATCH * 3000];
__device__ __half2 g_hC[(long long)BATCH * 1875];
__device__ __half2 g_hW[606080];

__device__ __forceinline__ __half2 split2(float v) {
    const __half hi = __float2half_rn(v);
    return __halves2half2(hi, __float2half_rn(v - __half2float(hi)));
}

__device__ __forceinline__ void ffma2(float2& d, const float2& a, const float2& b) {
    unsigned long long& dd = reinterpret_cast<unsigned long long&>(d);
    const unsigned long long& aa = reinterpret_cast<const unsigned long long&>(a);
    const unsigned long long& bb = reinterpret_cast<const unsigned long long&>(b);
    asm("fma.rn.f32x2 %0, %1, %2, %0;" : "+l"(dd) : "l"(aa), "l"(bb));
}

// ---------------- weight pre-split (single launch, 6 weights) ----------------
__global__ void split_w6(const float* __restrict__ w1, const float* __restrict__ w2,
                         const float* __restrict__ wa, const float* __restrict__ w0,
                         const float* __restrict__ wb2, const float* __restrict__ wc2,
                         __half2* __restrict__ o)
{
    const int i = blockIdx.x * 256 + threadIdx.x;
    if (i >= 606075) return;
    const float* s; int off;
    if      (i <   3750) { s = w1;  off = 0; }
    else if (i <  22500) { s = w2;  off = 3750; }
    else if (i <  31875) { s = wa;  off = 22500; }
    else if (i < 106875) { s = w0;  off = 31875; }
    else if (i < 414075) { s = wb2; off = 106875; }
    else                 { s = wc2; off = 414075; }
    o[i] = split2(s[i - off]);
}

// ============================================================================
// Fused stage 0 (R11, proven)
// ============================================================================
__global__ void __launch_bounds__(256)
stage0_fused(const float* __restrict__ X,
             const float* __restrict__ w0a, const float* __restrict__ b0a,
             const float* __restrict__ wl0, const float* __restrict__ bl0,
             const float* __restrict__ w0b, const float* __restrict__ b0b,
             const float* __restrict__ w0c, const float* __restrict__ b0c,
             const float* __restrict__ wr0, const float* __restrict__ br0,
             float* __restrict__ x1, __half2* __restrict__ hX)
{
    constexpr int ITEMS = 4;
    constexpr int W0A = 0, B0A = 15, WL0 = 20, BL0 = 506, WR0 = 524, BR0 = 1010,
                  W0B = 1028, B0B = 1403, W0C = 1428, B0C = 1453, WTOT = 1478;
    constexpr int PITEM = 1352;
    __shared__ float sm[WTOT + ITEMS * PITEM];

    const int tid = threadIdx.x;
    const long long base = (long long)blockIdx.x * ITEMS;

    for (int i = tid; i < WTOT; i += 256) {
        float v;
        if      (i < B0A) v = w0a[i - W0A];
        else if (i < WL0) v = b0a[i - B0A];
        else if (i < BL0) v = wl0[i - WL0];
        else if (i < WR0) v = bl0[i - BL0];
        else if (i < BR0) v = wr0[i - WR0];
        else if (i < W0B) v = br0[i - BR0];
        else if (i < B0B) v = w0b[i - W0B];
        else if (i < W0C) v = b0b[i - B0B];
        else if (i < B0C) v = w0c[i - W0C];
        else              v = b0c[i - B0C];
        sm[i] = v;
    }
    for (int i = tid; i < ITEMS * 135; i += 256) {
        const int it = i / 135, j = i - it * 135;
        sm[WTOT + it * PITEM + j] = X[(base + it) * 135 + j];
    }
    __syncthreads();

    for (int i = tid; i < ITEMS * 675; i += 256) {
        const int it = i / 675, q = i - it * 675;
        const int oc = q / 135, hw = q - oc * 135;
        const int h = hw / 27, w = hw - h * 27;
        const float* xi = &sm[WTOT + it * PITEM];
        float v = sm[B0A + oc];
#pragma unroll
        for (int kh = 0; kh < 3; kh++) {
            const int ih = h + kh - 1;
            if ((unsigned)ih < 5u)
                v = fmaf(xi[ih * 27 + w], sm[W0A + oc * 3 + kh], v);
        }
        sm[WTOT + it * PITEM + 135 + q] = v;
    }
    __syncthreads();

    for (int i = tid; i < ITEMS * (450 + 90); i += 256) {
        if (i < ITEMS * 450) {
            const int it = i / 450, q = i - it * 450;
            const int rr = q / 18, o = q - rr * 18;
            const float* z0 = &sm[WTOT + it * PITEM + 135 + rr * 27];
            float v = sm[BL0 + o];
            const float* wl = &sm[WL0 + o * 27];
#pragma unroll
            for (int w = 0; w < 27; w++) v = fmaf(z0[w], wl[w], v);
            sm[WTOT + it * PITEM + 810 + rr * 18 + o] = fmaxf(v, 0.0f);
        } else {
            const int j = i - ITEMS * 450;
            const int it = j / 90, q = j - it * 90;
            const int h = q / 18, o = q - h * 18;
            const float* xi = &sm[WTOT + it * PITEM + h * 27];
            float v = sm[BR0 + o];
            const float* wr = &sm[WR0 + o * 27];
#pragma unroll
            for (int w = 0; w < 27; w++) v = fmaf(xi[w], wr[w], v);
            sm[WTOT + it * PITEM + 1261 + q] = v;
        }
    }
    __syncthreads();

    for (int i = tid; i < ITEMS * 2250; i += 256) {
        const int it = i / 2250, r = i - it * 2250;
        const int oc = r / 90, ho = r - oc * 90;
        const int h = ho / 18, o = ho - h * 18;
        const float* z1 = &sm[WTOT + it * PITEM + 810];
        float v = sm[B0B + oc];
#pragma unroll
        for (int ic = 0; ic < 5; ic++) {
#pragma unroll
            for (int kh = 0; kh < 3; kh++) {
                const int ih = h + kh - 1;
                if ((unsigned)ih < 5u)
                    v = fmaf(z1[(ic * 5 + ih) * 18 + o], sm[W0B + oc * 15 + ic * 3 + kh], v);
            }
        }
        const float y = sm[WTOT + it * PITEM + 1261 + h * 18 + o];
        v = fmaf(y, sm[W0C + oc], v) + sm[B0C + oc];
        const long long gidx = (base + it) * 2250 + r;
        x1[gidx] = v;
        hX[gidx] = split2(v);
    }
}

// ============================================================================
// SIMT fp32 GEMM with flat coalesced A staging (MODE 1 semi-linear layers).
// ============================================================================
template<int MODE,int KH,int BM,int BN,int BK,int TM,int TN,int N,int K,int RELU,int ACCUM,int HOUT,int FOUT>
__global__ void __launch_bounds__((BM/TM)*(BN/TN), 2)
gemm(const float* __restrict__ A, const float* __restrict__ W,
     const float* __restrict__ bias, float* __restrict__ Out, __half2* __restrict__ hOut,
     int IH, int IW, int PH, int SP, int OW, int abstride)
{
    constexpr int NT    = (BM/TM)*(BN/TN);
    constexpr int KITER = (K + BK - 1) / BK;
    constexpr bool KG   = (K % BK) != 0;
    constexpr bool NG   = (N % BN) != 0;
    constexpr bool FLAT = (MODE == 1 && KITER == 1 && !KG);
    constexpr int ROWS  = (BM > NT) ? BM/NT : 1;
    constexpr int KSL   = (NT > BM) ? NT/BM : 1;
    constexpr int AJ    = BK / KSL;
    static_assert(BK % KSL == 0, "");
    static_assert(TN % 2 == 0, "");

    __shared__ __align__(16) float sA[BK][2*BM + 4];
    __shared__ __align__(16) float sB[BK][BN + 4];

    const int tid = threadIdx.x;
    const int m0  = blockIdx.x * BM;
    const int n0  = blockIdx.y * BN;

    const int a_k0 = (NT > BM) ? (tid / BM) : 0;
    const float* Abase[ROWS];
    int oh_[ROWS], aml[ROWS];
    const int IHW = IH * IW;
    if constexpr (!FLAT) {
#pragma unroll
        for (int r = 0; r < ROWS; r++) {
            const int ml = (NT >= BM) ? (tid % BM) : (tid + r * NT);
            aml[r] = ml;
            const int m = m0 + ml;
            const int b = m / SP;
            const int s = m - b * SP;
            if (MODE == 0) {
                const int oh = s / OW;
                oh_[r] = oh;
                Abase[r] = A + (long long)b * abstride + (s - oh * OW);
            } else {
                oh_[r] = 0;
                Abase[r] = A + (long long)b * abstride + (long long)s * K;
            }
        }
    }

    const int tn = tid % (BN/TN);
    const int tm = tid / (BN/TN);

    float2 acc[TM][TN/2];
#pragma unroll
    for (int i = 0; i < TM; i++)
#pragma unroll
        for (int j = 0; j < TN/2; j++) acc[i][j] = make_float2(0.f, 0.f);

    for (int kt = 0; kt < KITER; kt++) {
        const int k0 = kt * BK;
        if constexpr (FLAT) {
            const float* Ablk = A + (long long)m0 * K;
#pragma unroll
            for (int i4 = tid * 4; i4 < BM * K; i4 += NT * 4) {
                const float4 v = *(const float4*)(Ablk + i4);
#pragma unroll
                for (int e = 0; e < 4; e++) {
                    const int idx = i4 + e;
                    const int m = idx / K;
                    const int k = idx - m * K;
                    const float val = (&v.x)[e];
                    *(float2*)&sA[k][2*m] = make_float2(val, val);
                }
            }
        } else {
#pragma unroll
            for (int r = 0; r < ROWS; r++) {
#pragma unroll
                for (int j = 0; j < AJ; j++) {
                    const int kl = a_k0 + KSL * j;
                    const int k  = k0 + kl;
                    float v = 0.0f;
                    if (!KG || k < K) {
                        if (MODE == 0) {
                            const int ic = k / KH;
                            const int kh = k - ic * KH;
                            const int ih = oh_[r] + kh - PH;
                            if ((unsigned)ih < (unsigned)IH)
                                v = Abase[r][ic * IHW + ih * IW];
                        } else {
                            v = Abase[r][k];
                        }
                    }
                    *(float2*)&sA[kl][2 * aml[r]] = make_float2(v, v);
                }
            }
        }
        constexpr int BTOT = BK * BN;
        constexpr int BIT  = (BTOT + NT - 1) / NT;
#pragma unroll
        for (int t = 0; t < BIT; t++) {
            const int idx = tid + t * NT;
            if (BTOT % NT == 0 || idx < BTOT) {
                const int kl = idx % BK;
                const int n  = idx / BK;
                const int k  = k0 + kl;
                const int nn = n0 + n;
                float v = 0.0f;
                if ((!KG || k < K) && (!NG || nn < N)) v = W[nn * K + k];
                sB[kl][n] = v;
            }
        }
        __syncthreads();

#pragma unroll
        for (int kk = 0; kk < BK; kk++) {
            float2 a2[TM], b2[TN/2];
            {
                const float4* pa = (const float4*)&sA[kk][2 * tm * TM];
#pragma unroll
                for (int q = 0; q < TM/2; q++) {
                    const float4 t4 = pa[q];
                    a2[2*q]   = make_float2(t4.x, t4.y);
                    a2[2*q+1] = make_float2(t4.z, t4.w);
                }
            }
            if constexpr (TN % 4 == 0) {
                const float4* pb = (const float4*)&sB[kk][tn * TN];
#pragma unroll
                for (int q = 0; q < TN/4; q++) {
                    const float4 t4 = pb[q];
                    b2[2*q]   = make_float2(t4.x, t4.y);
                    b2[2*q+1] = make_float2(t4.z, t4.w);
                }
            } else {
                const float2* pb = (const float2*)&sB[kk][tn * TN];
#pragma unroll
                for (int q = 0; q < TN/2; q++) b2[q] = pb[q];
            }
#pragma unroll
            for (int i = 0; i < TM; i++)
#pragma unroll
                for (int j = 0; j < TN/2; j++)
                    ffma2(acc[i][j], a2[i], b2[j]);
        }
        __syncthreads();
    }

#pragma unroll
    for (int i = 0; i < TM; i++) {
        const int m = m0 + tm * TM + i;
        const int b = m / SP;
        const int s = m - b * SP;
#pragma unroll
        for (int j = 0; j < TN/2; j++) {
#pragma unroll
            for (int h = 0; h < 2; h++) {
                const int n = n0 + tn * TN + 2*j + h;
                if (!NG || n < N) {
                    float v = (h ? acc[i][j].y : acc[i][j].x) + bias[n];
                    if (RELU) v = fmaxf(v, 0.0f);
                    long long o;
                    if (MODE == 0) o = (long long)b * (N * SP) + (long long)n * SP + s;
                    else           o = (long long)b * (SP * N) + (long long)s * N + n;
                    if (ACCUM) v += Out[o];
                    if (FOUT) Out[o] = v;
                    if (HOUT) hOut[o] = split2(v);
                }
            }
        }
    }
}

// ============================================================================
// Tensor-core conv GEMM v5: R11's proven scalar staging / fragment loads,
// tile 128(M) x 64(N) x 32(K), 256 threads (8 warps, warp-tile 32x32),
// double-buffered smem, register prefetch.
// ============================================================================
__device__ __forceinline__ void mma16816(float* c, const uint32_t* a, const uint32_t* b) {
    asm volatile(
        "mma.sync.aligned.m16n8k16.row.col.f32.f16.f16.f32 "
        "{%0,%1,%2,%3}, {%4,%5,%6,%7}, {%8,%9}, {%0,%1,%2,%3};"
        : "+f"(c[0]), "+f"(c[1]), "+f"(c[2]), "+f"(c[3])
        : "r"(a[0]), "r"(a[1]), "r"(a[2]), "r"(a[3]), "r"(b[0]), "r"(b[1]));
}

template<int KH,int N,int K,int ACCUM,int HOUT,int NB>
__global__ void __launch_bounds__(256, 3)
tconv(const __half2* __restrict__ Ah, const __half2* __restrict__ Wh,
      const float* __restrict__ bias, float* __restrict__ Out, __half2* __restrict__ hOut,
      int IH, int IW, int PH, int SP, int OW, int abstride)
{
    constexpr int BM = 128, BN = 64, BK = 32;
    constexpr int KITER = (K + BK - 1) / BK;
    constexpr int PAD   = 38;
    __shared__ __align__(16) __half sAhi[2][BM][PAD];
    __shared__ __align__(16) __half sAlo[2][BM][PAD];
    __shared__ __align__(16) __half sBhi[2][BN][PAD];
    __shared__ __align__(16) __half sBlo[2][BN][PAD];

    const int tid  = threadIdx.x;
    const int nb   = (int)(blockIdx.x % NB);
    const int mb   = (int)(blockIdx.x / NB);
    const int m0   = mb * BM;
    const int n0   = nb * BN;
    const int IHW  = IH * IW;

    // ---- A staging: thread owns row (tid&127), k slots ak0 + 2t (t<16) ----
    const int arow = tid & 127;
    const int ak0  = tid >> 7;                    // 0/1
    const int am   = m0 + arow;
    const int ab   = am / SP;
    const int as   = am - ab * SP;
    const int aoh  = as / OW;
    const __half2* Abase = Ah + (long long)ab * abstride + (as - aoh * OW);

    // ---- B staging: thread owns kl (tid&31), n slots bn0 + 8t (t<8) ----
    const int bkl = tid & 31;
    const int bn0 = tid >> 5;                     // 0..7

    const int warp = tid >> 5, lane = tid & 31;
    const int wm = (warp & 3) * 32;               // 4 m-warps
    const int wn = (warp >> 2) * 32;              // 2 n-warps
    const int gr = lane >> 2;
    const int gc = lane & 3;

    __half2 aR[16], bR[8];
    const __half2 Z2 = __float2half2_rn(0.0f);

    auto prefetch = [&](int kt) {
        const int k0 = kt * BK;
#pragma unroll
        for (int t = 0; t < 16; t++) {
            const int k = k0 + ak0 + 2 * t;
            __half2 v = Z2;
            if (K % BK == 0 || k < K) {
                const int ic = k / KH;
                const int kh = k - ic * KH;
                const int ih = aoh + kh - PH;
                if ((unsigned)ih < (unsigned)IH)
                    v = Abase[ic * IHW + ih * IW];
            }
            aR[t] = v;
        }
        const int kB = k0 + bkl;
#pragma unroll
        for (int t = 0; t < 8; t++) {
            const int nn = n0 + bn0 + 8 * t;
            __half2 v = Z2;
            if ((K % BK == 0 || kB < K) && (N % BN == 0 || nn < N))
                v = Wh[(long long)nn * K + kB];
            bR[t] = v;
        }
    };

    auto stage = [&](int p) {
#pragma unroll
        for (int t = 0; t < 16; t++) {
            const int kl = ak0 + 2 * t;
            sAhi[p][arow][kl] = __low2half(aR[t]);
            sAlo[p][arow][kl] = __high2half(aR[t]);
        }
#pragma unroll
        for (int t = 0; t < 8; t++) {
            const int nl = bn0 + 8 * t;
            sBhi[p][nl][bkl] = __low2half(bR[t]);
            sBlo[p][nl][bkl] = __high2half(bR[t]);
        }
    };

    float acc[2][4][4];
#pragma unroll
    for (int i = 0; i < 2; i++)
#pragma unroll
        for (int j = 0; j < 4; j++)
#pragma unroll
            for (int q = 0; q < 4; q++) acc[i][j][q] = 0.0f;

    auto compute = [&](int p) {
#pragma unroll
        for (int ck = 0; ck < BK / 16; ck++) {
            const int kb = ck * 16 + 2 * gc;
            uint32_t ahi[2][4], alo[2][4], bhi[4][2], blo[4][2];
#pragma unroll
            for (int ms = 0; ms < 2; ms++) {
                const int r0 = wm + ms * 16 + gr;
                ahi[ms][0] = *(const uint32_t*)&sAhi[p][r0    ][kb    ];
                ahi[ms][1] = *(const uint32_t*)&sAhi[p][r0 + 8][kb    ];
                ahi[ms][2] = *(const uint32_t*)&sAhi[p][r0    ][kb + 8];
                ahi[ms][3] = *(const uint32_t*)&sAhi[p][r0 + 8][kb + 8];
                alo[ms][0] = *(const uint32_t*)&sAlo[p][r0    ][kb    ];
                alo[ms][1] = *(const uint32_t*)&sAlo[p][r0 + 8][kb    ];
                alo[ms][2] = *(const uint32_t*)&sAlo[p][r0    ][kb + 8];
                alo[ms][3] = *(const uint32_t*)&sAlo[p][r0 + 8][kb + 8];
            }
#pragma unroll
            for (int ns = 0; ns < 4; ns++) {
                const int nr = wn + ns * 8 + gr;
                bhi[ns][0] = *(const uint32_t*)&sBhi[p][nr][kb    ];
                bhi[ns][1] = *(const uint32_t*)&sBhi[p][nr][kb + 8];
                blo[ns][0] = *(const uint32_t*)&sBlo[p][nr][kb    ];
                blo[ns][1] = *(const uint32_t*)&sBlo[p][nr][kb + 8];
            }
#pragma unroll
            for (int ms = 0; ms < 2; ms++)
#pragma unroll
                for (int ns = 0; ns < 4; ns++) {
                    mma16816(acc[ms][ns], ahi[ms], bhi[ns]);
                    mma16816(acc[ms][ns], ahi[ms], blo[ns]);
                    mma16816(acc[ms][ns], alo[ms], bhi[ns]);
                }
        }
    };

    prefetch(0);
    stage(0);
    __syncthreads();
    for (int kt = 0; kt < KITER; kt++) {
        if (kt + 1 < KITER) prefetch(kt + 1);
        compute(kt & 1);
        if (kt + 1 < KITER) {
            stage((kt + 1) & 1);
            __syncthreads();
        }
    }

#pragma unroll
    for (int ms = 0; ms < 2; ms++) {
        const int mr0 = m0 + wm + ms * 16 + gr;
#pragma unroll
        for (int half = 0; half < 2; half++) {
            const int m = mr0 + half * 8;
            const int b = m / SP;
            const int s = m - b * SP;
            const long long obase = (long long)b * (N * SP) + s;
#pragma unroll
            for (int ns = 0; ns < 4; ns++) {
                const int n = n0 + wn + ns * 8 + 2 * gc;
#pragma unroll
                for (int e = 0; e < 2; e++) {
                    const int nn = n + e;
                    if (N % BN == 0 || nn < N) {
                        float v = acc[ms][ns][half * 2 + e] + bias[nn];
                        const long long o = obase + (long long)nn * SP;
                        if (ACCUM) v += Out[o];
                        Out[o] = v;
                        if (HOUT) hOut[o] = split2(v);
                    }
                }
            }
        }
    }
}

// ---------------- host-side typed launchers ----------------
template<int KH,int N,int K,int ACCUM,int HOUT>
static void tconv_l(const __half2* A, const __half2* W, const float* b, float* O,
                    __half2* hO, int IH, int IW, int PH)
{
    constexpr int NB = (N + 63) / 64;
    const int OH = IH + 2*PH - KH + 1, OW = IW, SP = OH * OW;
    const long long M = (long long)BATCH * SP;
    dim3 g((unsigned)((M / 128) * NB));
    tconv<KH,N,K,ACCUM,HOUT,NB><<<g, 256>>>(A, W, b, O, hO, IH, IW, PH, SP, OW, (K/KH)*IH*IW);
}

template<int BN,int BK,int TM,int TN,int N,int K,int RELU,int HOUT,int FOUT>
static void sl(const float* A, const float* W, const float* b, float* O, __half2* hO, int SP)
{
    constexpr int BM = 128;
    const long long M = (long long)BATCH * SP;
    dim3 g((unsigned)(M / BM), (N + BN - 1) / BN);
    gemm<1,1,BM,BN,BK,TM,TN,N,K,RELU,0,HOUT,FOUT><<<g, (BM/TM)*(BN/TN)>>>(
        A, W, b, O, hO, 1, 1, 0, SP, 1, SP*K);
}

extern "C" void kernel_launch(void* const* d_in, const int* in_sizes, int n_in,
                              void* d_out, int out_size)
{
    (void)in_sizes; (void)n_in; (void)out_size;
    const float* x    = (const float*)d_in[0];
    const float* w0a  = (const float*)d_in[1];  const float* b0a  = (const float*)d_in[2];
    const float* wl0  = (const float*)d_in[3];  const float* bl0  = (const float*)d_in[4];
    const float* w0b  = (const float*)d_in[5];  const float* b0b  = (const float*)d_in[6];
    const float* w0c  = (const float*)d_in[7];  const float* b0c  = (const float*)d_in[8];
    const float* wr0  = (const float*)d_in[9];  const float* br0  = (const float*)d_in[10];
    const float* w1   = (const float*)d_in[11]; const float* b1   = (const float*)d_in[12];
    const float* wl1  = (const float*)d_in[13]; const float* bl1  = (const float*)d_in[14];
    const float* w2   = (const float*)d_in[15]; const float* b2   = (const float*)d_in[16];
    const float* wa   = (const float*)d_in[17]; const float* ba   = (const float*)d_in[18];
    const float* wra  = (const float*)d_in[19]; const float* bra  = (const float*)d_in[20];
    const float* w0   = (const float*)d_in[21]; const float* b0   = (const float*)d_in[22];
    const float* wl2  = (const float*)d_in[23]; const float* bl2  = (const float*)d_in[24];
    const float* w0b2 = (const float*)d_in[25]; const float* b0b2 = (const float*)d_in[26];
    const float* w0c2 = (const float*)d_in[27]; const float* b0c2 = (const float*)d_in[28];
    const float* wr02 = (const float*)d_in[29]; const float* br02 = (const float*)d_in[30];
    float* out = (float*)d_out;

    float *A, *Bb, *C, *x1, *x2;
    __half2 *hX, *hB, *hC, *hW;
    cudaGetSymbolAddress((void**)&A,  g_bufA);
    cudaGetSymbolAddress((void**)&Bb, g_bufB);
    cudaGetSymbolAddress((void**)&C,  g_bufC);
    cudaGetSymbolAddress((void**)&x1, g_x1);
    cudaGetSymbolAddress((void**)&x2, g_x2);
    cudaGetSymbolAddress((void**)&hX, g_hX);
    cudaGetSymbolAddress((void**)&hB, g_hB);
    cudaGetSymbolAddress((void**)&hC, g_hC);
    cudaGetSymbolAddress((void**)&hW, g_hW);

    __half2* hw1   = hW;            // 3750
    __half2* hw2   = hW + 3750;     // 18750
    __half2* hwa   = hW + 22500;    // 9375
    __half2* hw0   = hW + 31875;    // 75000
    __half2* hw0b2 = hW + 106875;   // 307200
    __half2* hw0c2 = hW + 414075;   // 192000
    split_w6<<<(606075 + 255) / 256, 256>>>(w1, w2, wa, w0, w0b2, w0c2, hW);

    // ---- stage 0: single fused kernel -> x1 + hX ----
    stage0_fused<<<BATCH / 4, 256>>>(x, w0a, b0a, wl0, bl0, w0b, b0b,
                                     w0c, b0c, wr0, br0, x1, hX);

    // ---- stage 1 ----
    tconv_l<2,  75,  50, 0,0>(hX, hw1, b1, A, nullptr, 5, 18, 0);
    sl<16,18, 8,4, 10,18, 1,1,0>(A,  wl1, bl1, Bb, hB, 300);   // relu, half only
    tconv_l<2, 125, 150, 0,0>(hB, hw2, b2, x2, nullptr, 4, 10, 0);
    sl<16,18, 8,4, 10,18, 0,1,0>(x1, wra, bra, C,  hC, 125);   // half only
    tconv_l<3, 125,  75, 1,1>(hC, hwa, ba, x2, hX, 5, 10, 0);  // += y, x2 + half

    // ---- stage 2 ----
    tconv_l<2, 300, 250, 0,0>(hX, hw0, b0, A, nullptr, 3, 10, 0);
    sl< 8,10, 8,2,  5,10, 1,1,0>(A,  wl2, bl2, Bb, hB, 600);   // relu, half only
    tconv_l<2, 512, 600, 0,0>(hB, hw0b2, b0b2, out, nullptr, 2, 5, 0);
    sl< 8,10, 8,2,  5,10, 0,1,0>(x2, wr02, br02, C,  hC, 375); // half only
    tconv_l<3, 512, 375, 1,0>(hC, hw0c2, b0c2, out, nullptr, 3, 5, 0);
}

// round 14
// speedup vs baseline: 1.7217x; 1.7217x over previous
#include <cuda_runtime.h>
#include <cuda_fp16.h>
#include <cstdint>

#define BATCH 16384

// ---------------- static scratch (device globals; no allocations) ----------------
__device__ float g_bufA[(long long)BATCH * 6000];
__device__ float g_bufB[(long long)BATCH * 3000];
__device__ float g_bufC[(long long)BATCH * 1875];
__device__ float g_x1 [(long long)BATCH * 2250];
__device__ float g_x2 [(long long)BATCH * 3750];
// half (hi,lo) interleaved planes for tensor-core consumers
__device__ __half2 g_hX[(long long)BATCH * 3750];
__device__ __half2 g_hB[(long long)BATCH * 3000];
__device__ __half2 g_hC[(long long)BATCH * 1875];
__device__ __half2 g_hW[606080];

__device__ __forceinline__ __half2 split2(float v) {
    const __half hi = __float2half_rn(v);
    return __halves2half2(hi, __float2half_rn(v - __half2float(hi)));
}

__device__ __forceinline__ void ffma2(float2& d, const float2& a, const float2& b) {
    unsigned long long& dd = reinterpret_cast<unsigned long long&>(d);
    const unsigned long long& aa = reinterpret_cast<const unsigned long long&>(a);
    const unsigned long long& bb = reinterpret_cast<const unsigned long long&>(b);
    asm("fma.rn.f32x2 %0, %1, %2, %0;" : "+l"(dd) : "l"(aa), "l"(bb));
}

// ---------------- weight pre-split (single launch, 6 weights) ----------------
__global__ void split_w6(const float* __restrict__ w1, const float* __restrict__ w2,
                         const float* __restrict__ wa, const float* __restrict__ w0,
                         const float* __restrict__ wb2, const float* __restrict__ wc2,
                         __half2* __restrict__ o)
{
    const int i = blockIdx.x * 256 + threadIdx.x;
    if (i >= 606075) return;
    const float* s; int off;
    if      (i <   3750) { s = w1;  off = 0; }
    else if (i <  22500) { s = w2;  off = 3750; }
    else if (i <  31875) { s = wa;  off = 22500; }
    else if (i < 106875) { s = w0;  off = 31875; }
    else if (i < 414075) { s = wb2; off = 106875; }
    else                 { s = wc2; off = 414075; }
    o[i] = split2(s[i - off]);
}

// ============================================================================
// Fused stage 0 (R11, proven)
// ============================================================================
__global__ void __launch_bounds__(256)
stage0_fused(const float* __restrict__ X,
             const float* __restrict__ w0a, const float* __restrict__ b0a,
             const float* __restrict__ wl0, const float* __restrict__ bl0,
             const float* __restrict__ w0b, const float* __restrict__ b0b,
             const float* __restrict__ w0c, const float* __restrict__ b0c,
             const float* __restrict__ wr0, const float* __restrict__ br0,
             float* __restrict__ x1, __half2* __restrict__ hX)
{
    constexpr int ITEMS = 4;
    constexpr int W0A = 0, B0A = 15, WL0 = 20, BL0 = 506, WR0 = 524, BR0 = 1010,
                  W0B = 1028, B0B = 1403, W0C = 1428, B0C = 1453, WTOT = 1478;
    constexpr int PITEM = 1352;
    __shared__ float sm[WTOT + ITEMS * PITEM];

    const int tid = threadIdx.x;
    const long long base = (long long)blockIdx.x * ITEMS;

    for (int i = tid; i < WTOT; i += 256) {
        float v;
        if      (i < B0A) v = w0a[i - W0A];
        else if (i < WL0) v = b0a[i - B0A];
        else if (i < BL0) v = wl0[i - WL0];
        else if (i < WR0) v = bl0[i - BL0];
        else if (i < BR0) v = wr0[i - WR0];
        else if (i < W0B) v = br0[i - BR0];
        else if (i < B0B) v = w0b[i - W0B];
        else if (i < W0C) v = b0b[i - B0B];
        else if (i < B0C) v = w0c[i - W0C];
        else              v = b0c[i - B0C];
        sm[i] = v;
    }
    for (int i = tid; i < ITEMS * 135; i += 256) {
        const int it = i / 135, j = i - it * 135;
        sm[WTOT + it * PITEM + j] = X[(base + it) * 135 + j];
    }
    __syncthreads();

    for (int i = tid; i < ITEMS * 675; i += 256) {
        const int it = i / 675, q = i - it * 675;
        const int oc = q / 135, hw = q - oc * 135;
        const int h = hw / 27, w = hw - h * 27;
        const float* xi = &sm[WTOT + it * PITEM];
        float v = sm[B0A + oc];
#pragma unroll
        for (int kh = 0; kh < 3; kh++) {
            const int ih = h + kh - 1;
            if ((unsigned)ih < 5u)
                v = fmaf(xi[ih * 27 + w], sm[W0A + oc * 3 + kh], v);
        }
        sm[WTOT + it * PITEM + 135 + q] = v;
    }
    __syncthreads();

    for (int i = tid; i < ITEMS * (450 + 90); i += 256) {
        if (i < ITEMS * 450) {
            const int it = i / 450, q = i - it * 450;
            const int rr = q / 18, o = q - rr * 18;
            const float* z0 = &sm[WTOT + it * PITEM + 135 + rr * 27];
            float v = sm[BL0 + o];
            const float* wl = &sm[WL0 + o * 27];
#pragma unroll
            for (int w = 0; w < 27; w++) v = fmaf(z0[w], wl[w], v);
            sm[WTOT + it * PITEM + 810 + rr * 18 + o] = fmaxf(v, 0.0f);
        } else {
            const int j = i - ITEMS * 450;
            const int it = j / 90, q = j - it * 90;
            const int h = q / 18, o = q - h * 18;
            const float* xi = &sm[WTOT + it * PITEM + h * 27];
            float v = sm[BR0 + o];
            const float* wr = &sm[WR0 + o * 27];
#pragma unroll
            for (int w = 0; w < 27; w++) v = fmaf(xi[w], wr[w], v);
            sm[WTOT + it * PITEM + 1261 + q] = v;
        }
    }
    __syncthreads();

    for (int i = tid; i < ITEMS * 2250; i += 256) {
        const int it = i / 2250, r = i - it * 2250;
        const int oc = r / 90, ho = r - oc * 90;
        const int h = ho / 18, o = ho - h * 18;
        const float* z1 = &sm[WTOT + it * PITEM + 810];
        float v = sm[B0B + oc];
#pragma unroll
        for (int ic = 0; ic < 5; ic++) {
#pragma unroll
            for (int kh = 0; kh < 3; kh++) {
                const int ih = h + kh - 1;
                if ((unsigned)ih < 5u)
                    v = fmaf(z1[(ic * 5 + ih) * 18 + o], sm[W0B + oc * 15 + ic * 3 + kh], v);
            }
        }
        const float y = sm[WTOT + it * PITEM + 1261 + h * 18 + o];
        v = fmaf(y, sm[W0C + oc], v) + sm[B0C + oc];
        const long long gidx = (base + it) * 2250 + r;
        x1[gidx] = v;
        hX[gidx] = split2(v);
    }
}

// ============================================================================
// SIMT fp32 GEMM, flat coalesced A staging (used ONLY by semi-linear layers).
// ============================================================================
template<int MODE,int KH,int BM,int BN,int BK,int TM,int TN,int N,int K,int RELU,int ACCUM,int HOUT,int FOUT>
__global__ void __launch_bounds__((BM/TM)*(BN/TN), 4)
gemm(const float* __restrict__ A, const float* __restrict__ W,
     const float* __restrict__ bias, float* __restrict__ Out, __half2* __restrict__ hOut,
     int IH, int IW, int PH, int SP, int OW, int abstride)
{
    constexpr int NT    = (BM/TM)*(BN/TN);
    constexpr int KITER = (K + BK - 1) / BK;
    constexpr bool KG   = (K % BK) != 0;
    constexpr bool NG   = (N % BN) != 0;
    constexpr bool FLAT = (MODE == 1 && KITER == 1 && !KG);
    constexpr int ROWS  = (BM > NT) ? BM/NT : 1;
    constexpr int KSL   = (NT > BM) ? NT/BM : 1;
    constexpr int AJ    = BK / KSL;
    static_assert(BK % KSL == 0, "");
    static_assert(TN % 2 == 0, "");

    __shared__ __align__(16) float sA[BK][2*BM + 4];
    __shared__ __align__(16) float sB[BK][BN + 4];

    const int tid = threadIdx.x;
    const int m0  = blockIdx.x * BM;
    const int n0  = blockIdx.y * BN;

    const int a_k0 = (NT > BM) ? (tid / BM) : 0;
    const float* Abase[ROWS];
    int oh_[ROWS], aml[ROWS];
    const int IHW = IH * IW;
    if constexpr (!FLAT) {
#pragma unroll
        for (int r = 0; r < ROWS; r++) {
            const int ml = (NT >= BM) ? (tid % BM) : (tid + r * NT);
            aml[r] = ml;
            const int m = m0 + ml;
            const int b = m / SP;
            const int s = m - b * SP;
            if (MODE == 0) {
                const int oh = s / OW;
                oh_[r] = oh;
                Abase[r] = A + (long long)b * abstride + (s - oh * OW);
            } else {
                oh_[r] = 0;
                Abase[r] = A + (long long)b * abstride + (long long)s * K;
            }
        }
    }

    const int tn = tid % (BN/TN);
    const int tm = tid / (BN/TN);

    float2 acc[TM][TN/2];
#pragma unroll
    for (int i = 0; i < TM; i++)
#pragma unroll
        for (int j = 0; j < TN/2; j++) acc[i][j] = make_float2(0.f, 0.f);

    for (int kt = 0; kt < KITER; kt++) {
        const int k0 = kt * BK;
        if constexpr (FLAT) {
            const float* Ablk = A + (long long)m0 * K;
#pragma unroll
            for (int i4 = tid * 4; i4 < BM * K; i4 += NT * 4) {
                const float4 v = *(const float4*)(Ablk + i4);
#pragma unroll
                for (int e = 0; e < 4; e++) {
                    const int idx = i4 + e;
                    const int m = idx / K;
                    const int k = idx - m * K;
                    const float val = (&v.x)[e];
                    *(float2*)&sA[k][2*m] = make_float2(val, val);
                }
            }
        } else {
#pragma unroll
            for (int r = 0; r < ROWS; r++) {
#pragma unroll
                for (int j = 0; j < AJ; j++) {
                    const int kl = a_k0 + KSL * j;
                    const int k  = k0 + kl;
                    float v = 0.0f;
                    if (!KG || k < K) {
                        if (MODE == 0) {
                            const int ic = k / KH;
                            const int kh = k - ic * KH;
                            const int ih = oh_[r] + kh - PH;
                            if ((unsigned)ih < (unsigned)IH)
                                v = Abase[r][ic * IHW + ih * IW];
                        } else {
                            v = Abase[r][k];
                        }
                    }
                    *(float2*)&sA[kl][2 * aml[r]] = make_float2(v, v);
                }
            }
        }
        constexpr int BTOT = BK * BN;
        constexpr int BIT  = (BTOT + NT - 1) / NT;
#pragma unroll
        for (int t = 0; t < BIT; t++) {
            const int idx = tid + t * NT;
            if (BTOT % NT == 0 || idx < BTOT) {
                const int kl = idx % BK;
                const int n  = idx / BK;
                const int k  = k0 + kl;
                const int nn = n0 + n;
                float v = 0.0f;
                if ((!KG || k < K) && (!NG || nn < N)) v = W[nn * K + k];
                sB[kl][n] = v;
            }
        }
        __syncthreads();

#pragma unroll
        for (int kk = 0; kk < BK; kk++) {
            float2 a2[TM], b2[TN/2];
            {
                const float4* pa = (const float4*)&sA[kk][2 * tm * TM];
#pragma unroll
                for (int q = 0; q < TM/2; q++) {
                    const float4 t4 = pa[q];
                    a2[2*q]   = make_float2(t4.x, t4.y);
                    a2[2*q+1] = make_float2(t4.z, t4.w);
                }
            }
            if constexpr (TN % 4 == 0) {
                const float4* pb = (const float4*)&sB[kk][tn * TN];
#pragma unroll
                for (int q = 0; q < TN/4; q++) {
                    const float4 t4 = pb[q];
                    b2[2*q]   = make_float2(t4.x, t4.y);
                    b2[2*q+1] = make_float2(t4.z, t4.w);
                }
            } else {
                const float2* pb = (const float2*)&sB[kk][tn * TN];
#pragma unroll
                for (int q = 0; q < TN/2; q++) b2[q] = pb[q];
            }
#pragma unroll
            for (int i = 0; i < TM; i++)
#pragma unroll
                for (int j = 0; j < TN/2; j++)
                    ffma2(acc[i][j], a2[i], b2[j]);
        }
        __syncthreads();
    }

#pragma unroll
    for (int i = 0; i < TM; i++) {
        const int m = m0 + tm * TM + i;
        const int b = m / SP;
        const int s = m - b * SP;
#pragma unroll
        for (int j = 0; j < TN/2; j++) {
#pragma unroll
            for (int h = 0; h < 2; h++) {
                const int n = n0 + tn * TN + 2*j + h;
                if (!NG || n < N) {
                    float v = (h ? acc[i][j].y : acc[i][j].x) + bias[n];
                    if (RELU) v = fmaxf(v, 0.0f);
                    long long o;
                    if (MODE == 0) o = (long long)b * (N * SP) + (long long)n * SP + s;
                    else           o = (long long)b * (SP * N) + (long long)s * N + n;
                    if (ACCUM) v += Out[o];
                    if (FOUT) Out[o] = v;
                    if (HOUT) hOut[o] = split2(v);
                }
            }
        }
    }
}

// ============================================================================
// Tensor-core conv GEMM v5b: R11 staging/fragment code, tile 128x64x32,
// 256 threads (8 warps, warp-tile 32x32), launch_bounds(256,2) -> 128 regs,
// double-buffered smem, register prefetch.
// ============================================================================
__device__ __forceinline__ void mma16816(float* c, const uint32_t* a, const uint32_t* b) {
    asm volatile(
        "mma.sync.aligned.m16n8k16.row.col.f32.f16.f16.f32 "
        "{%0,%1,%2,%3}, {%4,%5,%6,%7}, {%8,%9}, {%0,%1,%2,%3};"
        : "+f"(c[0]), "+f"(c[1]), "+f"(c[2]), "+f"(c[3])
        : "r"(a[0]), "r"(a[1]), "r"(a[2]), "r"(a[3]), "r"(b[0]), "r"(b[1]));
}

template<int KH,int N,int K,int ACCUM,int HOUT,int NB>
__global__ void __launch_bounds__(256, 2)
tconv(const __half2* __restrict__ Ah, const __half2* __restrict__ Wh,
      const float* __restrict__ bias, float* __restrict__ Out, __half2* __restrict__ hOut,
      int IH, int IW, int PH, int SP, int OW, int abstride)
{
    constexpr int BM = 128, BN = 64, BK = 32;
    constexpr int KITER = (K + BK - 1) / BK;
    constexpr int PAD   = 38;
    __shared__ __align__(16) __half sAhi[2][BM][PAD];
    __shared__ __align__(16) __half sAlo[2][BM][PAD];
    __shared__ __align__(16) __half sBhi[2][BN][PAD];
    __shared__ __align__(16) __half sBlo[2][BN][PAD];

    const int tid  = threadIdx.x;
    const int nb   = (int)(blockIdx.x % NB);
    const int mb   = (int)(blockIdx.x / NB);
    const int m0   = mb * BM;
    const int n0   = nb * BN;
    const int IHW  = IH * IW;

    // ---- A staging: thread owns row (tid&127), k slots ak0 + 2t (t<16) ----
    const int arow = tid & 127;
    const int ak0  = tid >> 7;                    // 0/1
    const int am   = m0 + arow;
    const int ab   = am / SP;
    const int as   = am - ab * SP;
    const int aoh  = as / OW;
    const __half2* Abase = Ah + (long long)ab * abstride + (as - aoh * OW);

    // ---- B staging: thread owns kl (tid&31), n slots bn0 + 8t (t<8) ----
    const int bkl = tid & 31;
    const int bn0 = tid >> 5;                     // 0..7

    const int warp = tid >> 5, lane = tid & 31;
    const int wm = (warp & 3) * 32;               // 4 m-warps
    const int wn = (warp >> 2) * 32;              // 2 n-warps
    const int gr = lane >> 2;
    const int gc = lane & 3;

    __half2 aR[16], bR[8];
    const __half2 Z2 = __float2half2_rn(0.0f);

    auto prefetch = [&](int kt) {
        const int k0 = kt * BK;
#pragma unroll
        for (int t = 0; t < 16; t++) {
            const int k = k0 + ak0 + 2 * t;
            __half2 v = Z2;
            if (K % BK == 0 || k < K) {
                const int ic = k / KH;
                const int kh = k - ic * KH;
                const int ih = aoh + kh - PH;
                if ((unsigned)ih < (unsigned)IH)
                    v = Abase[ic * IHW + ih * IW];
            }
            aR[t] = v;
        }
        const int kB = k0 + bkl;
#pragma unroll
        for (int t = 0; t < 8; t++) {
            const int nn = n0 + bn0 + 8 * t;
            __half2 v = Z2;
            if ((K % BK == 0 || kB < K) && (N % BN == 0 || nn < N))
                v = Wh[(long long)nn * K + kB];
            bR[t] = v;
        }
    };

    auto stage = [&](int p) {
#pragma unroll
        for (int t = 0; t < 16; t++) {
            const int kl = ak0 + 2 * t;
            sAhi[p][arow][kl] = __low2half(aR[t]);
            sAlo[p][arow][kl] = __high2half(aR[t]);
        }
#pragma unroll
        for (int t = 0; t < 8; t++) {
            const int nl = bn0 + 8 * t;
            sBhi[p][nl][bkl] = __low2half(bR[t]);
            sBlo[p][nl][bkl] = __high2half(bR[t]);
        }
    };

    float acc[2][4][4];
#pragma unroll
    for (int i = 0; i < 2; i++)
#pragma unroll
        for (int j = 0; j < 4; j++)
#pragma unroll
            for (int q = 0; q < 4; q++) acc[i][j][q] = 0.0f;

    auto compute = [&](int p) {
#pragma unroll
        for (int ck = 0; ck < BK / 16; ck++) {
            const int kb = ck * 16 + 2 * gc;
            uint32_t ahi[2][4], alo[2][4], bhi[4][2], blo[4][2];
#pragma unroll
            for (int ms = 0; ms < 2; ms++) {
                const int r0 = wm + ms * 16 + gr;
                ahi[ms][0] = *(const uint32_t*)&sAhi[p][r0    ][kb    ];
                ahi[ms][1] = *(const uint32_t*)&sAhi[p][r0 + 8][kb    ];
                ahi[ms][2] = *(const uint32_t*)&sAhi[p][r0    ][kb + 8];
                ahi[ms][3] = *(const uint32_t*)&sAhi[p][r0 + 8][kb + 8];
                alo[ms][0] = *(const uint32_t*)&sAlo[p][r0    ][kb    ];
                alo[ms][1] = *(const uint32_t*)&sAlo[p][r0 + 8][kb    ];
                alo[ms][2] = *(const uint32_t*)&sAlo[p][r0    ][kb + 8];
                alo[ms][3] = *(const uint32_t*)&sAlo[p][r0 + 8][kb + 8];
            }
#pragma unroll
            for (int ns = 0; ns < 4; ns++) {
                const int nr = wn + ns * 8 + gr;
                bhi[ns][0] = *(const uint32_t*)&sBhi[p][nr][kb    ];
                bhi[ns][1] = *(const uint32_t*)&sBhi[p][nr][kb + 8];
                blo[ns][0] = *(const uint32_t*)&sBlo[p][nr][kb    ];
                blo[ns][1] = *(const uint32_t*)&sBlo[p][nr][kb + 8];
            }
#pragma unroll
            for (int ms = 0; ms < 2; ms++)
#pragma unroll
                for (int ns = 0; ns < 4; ns++) {
                    mma16816(acc[ms][ns], ahi[ms], bhi[ns]);
                    mma16816(acc[ms][ns], ahi[ms], blo[ns]);
                    mma16816(acc[ms][ns], alo[ms], bhi[ns]);
                }
        }
    };

    prefetch(0);
    stage(0);
    __syncthreads();
    for (int kt = 0; kt < KITER; kt++) {
        if (kt + 1 < KITER) prefetch(kt + 1);
        compute(kt & 1);
        if (kt + 1 < KITER) {
            stage((kt + 1) & 1);
            __syncthreads();
        }
    }

#pragma unroll
    for (int ms = 0; ms < 2; ms++) {
        const int mr0 = m0 + wm + ms * 16 + gr;
#pragma unroll
        for (int half = 0; half < 2; half++) {
            const int m = mr0 + half * 8;
            const int b = m / SP;
            const int s = m - b * SP;
            const long long obase = (long long)b * (N * SP) + s;
#pragma unroll
            for (int ns = 0; ns < 4; ns++) {
                const int n = n0 + wn + ns * 8 + 2 * gc;
#pragma unroll
                for (int e = 0; e < 2; e++) {
                    const int nn = n + e;
                    if (N % BN == 0 || nn < N) {
                        float v = acc[ms][ns][half * 2 + e] + bias[nn];
                        const long long o = obase + (long long)nn * SP;
                        if (ACCUM) v += Out[o];
                        Out[o] = v;
                        if (HOUT) hOut[o] = split2(v);
                    }
                }
            }
        }
    }
}

// ---------------- host-side typed launchers ----------------
template<int KH,int N,int K,int ACCUM,int HOUT>
static void tconv_l(const __half2* A, const __half2* W, const float* b, float* O,
                    __half2* hO, int IH, int IW, int PH)
{
    constexpr int NB = (N + 63) / 64;
    const int OH = IH + 2*PH - KH + 1, OW = IW, SP = OH * OW;
    const long long M = (long long)BATCH * SP;
    dim3 g((unsigned)((M / 128) * NB));
    tconv<KH,N,K,ACCUM,HOUT,NB><<<g, 256>>>(A, W, b, O, hO, IH, IW, PH, SP, OW, (K/KH)*IH*IW);
}

template<int BN,int BK,int TM,int TN,int N,int K,int RELU,int HOUT,int FOUT>
static void sl(const float* A, const float* W, const float* b, float* O, __half2* hO, int SP)
{
    constexpr int BM = 128;
    const long long M = (long long)BATCH * SP;
    dim3 g((unsigned)(M / BM), (N + BN - 1) / BN);
    gemm<1,1,BM,BN,BK,TM,TN,N,K,RELU,0,HOUT,FOUT><<<g, (BM/TM)*(BN/TN)>>>(
        A, W, b, O, hO, 1, 1, 0, SP, 1, SP*K);
}

extern "C" void kernel_launch(void* const* d_in, const int* in_sizes, int n_in,
                              void* d_out, int out_size)
{
    (void)in_sizes; (void)n_in; (void)out_size;
    const float* x    = (const float*)d_in[0];
    const float* w0a  = (const float*)d_in[1];  const float* b0a  = (const float*)d_in[2];
    const float* wl0  = (const float*)d_in[3];  const float* bl0  = (const float*)d_in[4];
    const float* w0b  = (const float*)d_in[5];  const float* b0b  = (const float*)d_in[6];
    const float* w0c  = (const float*)d_in[7];  const float* b0c  = (const float*)d_in[8];
    const float* wr0  = (const float*)d_in[9];  const float* br0  = (const float*)d_in[10];
    const float* w1   = (const float*)d_in[11]; const float* b1   = (const float*)d_in[12];
    const float* wl1  = (const float*)d_in[13]; const float* bl1  = (const float*)d_in[14];
    const float* w2   = (const float*)d_in[15]; const float* b2   = (const float*)d_in[16];
    const float* wa   = (const float*)d_in[17]; const float* ba   = (const float*)d_in[18];
    const float* wra  = (const float*)d_in[19]; const float* bra  = (const float*)d_in[20];
    const float* w0   = (const float*)d_in[21]; const float* b0   = (const float*)d_in[22];
    const float* wl2  = (const float*)d_in[23]; const float* bl2  = (const float*)d_in[24];
    const float* w0b2 = (const float*)d_in[25]; const float* b0b2 = (const float*)d_in[26];
    const float* w0c2 = (const float*)d_in[27]; const float* b0c2 = (const float*)d_in[28];
    const float* wr02 = (const float*)d_in[29]; const float* br02 = (const float*)d_in[30];
    float* out = (float*)d_out;

    float *A, *Bb, *C, *x1, *x2;
    __half2 *hX, *hB, *hC, *hW;
    cudaGetSymbolAddress((void**)&A,  g_bufA);
    cudaGetSymbolAddress((void**)&Bb, g_bufB);
    cudaGetSymbolAddress((void**)&C,  g_bufC);
    cudaGetSymbolAddress((void**)&x1, g_x1);
    cudaGetSymbolAddress((void**)&x2, g_x2);
    cudaGetSymbolAddress((void**)&hX, g_hX);
    cudaGetSymbolAddress((void**)&hB, g_hB);
    cudaGetSymbolAddress((void**)&hC, g_hC);
    cudaGetSymbolAddress((void**)&hW, g_hW);

    __half2* hw1   = hW;            // 3750
    __half2* hw2   = hW + 3750;     // 18750
    __half2* hwa   = hW + 22500;    // 9375
    __half2* hw0   = hW + 31875;    // 75000
    __half2* hw0b2 = hW + 106875;   // 307200
    __half2* hw0c2 = hW + 414075;   // 192000
    split_w6<<<(606075 + 255) / 256, 256>>>(w1, w2, wa, w0, w0b2, w0c2, hW);

    // ---- stage 0: single fused kernel -> x1 + hX ----
    stage0_fused<<<BATCH / 4, 256>>>(x, w0a, b0a, wl0, bl0, w0b, b0b,
                                     w0c, b0c, wr0, br0, x1, hX);

    // ---- stage 1 ----
    tconv_l<2,  75,  50, 0,0>(hX, hw1, b1, A, nullptr, 5, 18, 0);
    sl<16,18, 4,4, 10,18, 1,1,0>(A,  wl1, bl1, Bb, hB, 300);   // relu, half only
    tconv_l<2, 125, 150, 0,0>(hB, hw2, b2, x2, nullptr, 4, 10, 0);
    sl<16,18, 4,4, 10,18, 0,1,0>(x1, wra, bra, C,  hC, 125);   // half only
    tconv_l<3, 125,  75, 1,1>(hC, hwa, ba, x2, hX, 5, 10, 0);  // += y, x2 + half

    // ---- stage 2 ----
    tconv_l<2, 300, 250, 0,0>(hX, hw0, b0, A, nullptr, 3, 10, 0);
    sl< 8,10, 4,2,  5,10, 1,1,0>(A,  wl2, bl2, Bb, hB, 600);   // relu, half only
    tconv_l<2, 512, 600, 0,0>(hB, hw0b2, b0b2, out, nullptr, 2, 5, 0);
    sl< 8,10, 4,2,  5,10, 0,1,0>(x2, wr02, br02, C,  hC, 375); // half only
    tconv_l<3, 512, 375, 1,0>(hC, hw0c2, b0c2, out, nullptr, 3, 5, 0);
}

// round 15
// speedup vs baseline: 1.7427x; 1.0122x over previous
#include <cuda_runtime.h>
#include <cuda_fp16.h>
#include <cstdint>

#define BATCH 16384

// ---------------- static scratch (device globals; no allocations) ----------------
__device__ float g_bufA[(long long)BATCH * 6000];
__device__ float g_bufB[(long long)BATCH * 3000];
__device__ float g_bufC[(long long)BATCH * 1875];
__device__ float g_x1 [(long long)BATCH * 2250];
__device__ float g_x2 [(long long)BATCH * 3750];
// half (hi,lo) interleaved planes for tensor-core consumers
__device__ __half2 g_hX[(long long)BATCH * 3750];
__device__ __half2 g_hB[(long long)BATCH * 3000];
__device__ __half2 g_hC[(long long)BATCH * 1875];
__device__ __half2 g_hW[606080];

__device__ __forceinline__ __half2 split2(float v) {
    const __half hi = __float2half_rn(v);
    return __halves2half2(hi, __float2half_rn(v - __half2float(hi)));
}

__device__ __forceinline__ void ffma2(float2& d, const float2& a, const float2& b) {
    unsigned long long& dd = reinterpret_cast<unsigned long long&>(d);
    const unsigned long long& aa = reinterpret_cast<const unsigned long long&>(a);
    const unsigned long long& bb = reinterpret_cast<const unsigned long long&>(b);
    asm("fma.rn.f32x2 %0, %1, %2, %0;" : "+l"(dd) : "l"(aa), "l"(bb));
}

// ---------------- weight pre-split (single launch, 6 weights) ----------------
__global__ void split_w6(const float* __restrict__ w1, const float* __restrict__ w2,
                         const float* __restrict__ wa, const float* __restrict__ w0,
                         const float* __restrict__ wb2, const float* __restrict__ wc2,
                         __half2* __restrict__ o)
{
    const int i = blockIdx.x * 256 + threadIdx.x;
    if (i >= 606075) return;
    const float* s; int off;
    if      (i <   3750) { s = w1;  off = 0; }
    else if (i <  22500) { s = w2;  off = 3750; }
    else if (i <  31875) { s = wa;  off = 22500; }
    else if (i < 106875) { s = w0;  off = 31875; }
    else if (i < 414075) { s = wb2; off = 106875; }
    else                 { s = wc2; off = 414075; }
    o[i] = split2(s[i - off]);
}

// ============================================================================
// Fused stage 0 (R11, proven)
// ============================================================================
__global__ void __launch_bounds__(256)
stage0_fused(const float* __restrict__ X,
             const float* __restrict__ w0a, const float* __restrict__ b0a,
             const float* __restrict__ wl0, const float* __restrict__ bl0,
             const float* __restrict__ w0b, const float* __restrict__ b0b,
             const float* __restrict__ w0c, const float* __restrict__ b0c,
             const float* __restrict__ wr0, const float* __restrict__ br0,
             float* __restrict__ x1, __half2* __restrict__ hX)
{
    constexpr int ITEMS = 4;
    constexpr int W0A = 0, B0A = 15, WL0 = 20, BL0 = 506, WR0 = 524, BR0 = 1010,
                  W0B = 1028, B0B = 1403, W0C = 1428, B0C = 1453, WTOT = 1478;
    constexpr int PITEM = 1352;
    __shared__ float sm[WTOT + ITEMS * PITEM];

    const int tid = threadIdx.x;
    const long long base = (long long)blockIdx.x * ITEMS;

    for (int i = tid; i < WTOT; i += 256) {
        float v;
        if      (i < B0A) v = w0a[i - W0A];
        else if (i < WL0) v = b0a[i - B0A];
        else if (i < BL0) v = wl0[i - WL0];
        else if (i < WR0) v = bl0[i - BL0];
        else if (i < BR0) v = wr0[i - WR0];
        else if (i < W0B) v = br0[i - BR0];
        else if (i < B0B) v = w0b[i - W0B];
        else if (i < W0C) v = b0b[i - B0B];
        else if (i < B0C) v = w0c[i - W0C];
        else              v = b0c[i - B0C];
        sm[i] = v;
    }
    for (int i = tid; i < ITEMS * 135; i += 256) {
        const int it = i / 135, j = i - it * 135;
        sm[WTOT + it * PITEM + j] = X[(base + it) * 135 + j];
    }
    __syncthreads();

    for (int i = tid; i < ITEMS * 675; i += 256) {
        const int it = i / 675, q = i - it * 675;
        const int oc = q / 135, hw = q - oc * 135;
        const int h = hw / 27, w = hw - h * 27;
        const float* xi = &sm[WTOT + it * PITEM];
        float v = sm[B0A + oc];
#pragma unroll
        for (int kh = 0; kh < 3; kh++) {
            const int ih = h + kh - 1;
            if ((unsigned)ih < 5u)
                v = fmaf(xi[ih * 27 + w], sm[W0A + oc * 3 + kh], v);
        }
        sm[WTOT + it * PITEM + 135 + q] = v;
    }
    __syncthreads();

    for (int i = tid; i < ITEMS * (450 + 90); i += 256) {
        if (i < ITEMS * 450) {
            const int it = i / 450, q = i - it * 450;
            const int rr = q / 18, o = q - rr * 18;
            const float* z0 = &sm[WTOT + it * PITEM + 135 + rr * 27];
            float v = sm[BL0 + o];
            const float* wl = &sm[WL0 + o * 27];
#pragma unroll
            for (int w = 0; w < 27; w++) v = fmaf(z0[w], wl[w], v);
            sm[WTOT + it * PITEM + 810 + rr * 18 + o] = fmaxf(v, 0.0f);
        } else {
            const int j = i - ITEMS * 450;
            const int it = j / 90, q = j - it * 90;
            const int h = q / 18, o = q - h * 18;
            const float* xi = &sm[WTOT + it * PITEM + h * 27];
            float v = sm[BR0 + o];
            const float* wr = &sm[WR0 + o * 27];
#pragma unroll
            for (int w = 0; w < 27; w++) v = fmaf(xi[w], wr[w], v);
            sm[WTOT + it * PITEM + 1261 + q] = v;
        }
    }
    __syncthreads();

    for (int i = tid; i < ITEMS * 2250; i += 256) {
        const int it = i / 2250, r = i - it * 2250;
        const int oc = r / 90, ho = r - oc * 90;
        const int h = ho / 18, o = ho - h * 18;
        const float* z1 = &sm[WTOT + it * PITEM + 810];
        float v = sm[B0B + oc];
#pragma unroll
        for (int ic = 0; ic < 5; ic++) {
#pragma unroll
            for (int kh = 0; kh < 3; kh++) {
                const int ih = h + kh - 1;
                if ((unsigned)ih < 5u)
                    v = fmaf(z1[(ic * 5 + ih) * 18 + o], sm[W0B + oc * 15 + ic * 3 + kh], v);
            }
        }
        const float y = sm[WTOT + it * PITEM + 1261 + h * 18 + o];
        v = fmaf(y, sm[W0C + oc], v) + sm[B0C + oc];
        const long long gidx = (base + it) * 2250 + r;
        x1[gidx] = v;
        hX[gidx] = split2(v);
    }
}

// ============================================================================
// SIMT fp32 GEMM, flat coalesced A staging (used ONLY by semi-linear layers).
// R14 config: TM=4 -> ~90 regs, occ ~30%.
// ============================================================================
template<int MODE,int KH,int BM,int BN,int BK,int TM,int TN,int N,int K,int RELU,int ACCUM,int HOUT,int FOUT>
__global__ void __launch_bounds__((BM/TM)*(BN/TN), 4)
gemm(const float* __restrict__ A, const float* __restrict__ W,
     const float* __restrict__ bias, float* __restrict__ Out, __half2* __restrict__ hOut,
     int IH, int IW, int PH, int SP, int OW, int abstride)
{
    constexpr int NT    = (BM/TM)*(BN/TN);
    constexpr int KITER = (K + BK - 1) / BK;
    constexpr bool KG   = (K % BK) != 0;
    constexpr bool NG   = (N % BN) != 0;
    constexpr bool FLAT = (MODE == 1 && KITER == 1 && !KG);
    constexpr int ROWS  = (BM > NT) ? BM/NT : 1;
    constexpr int KSL   = (NT > BM) ? NT/BM : 1;
    constexpr int AJ    = BK / KSL;
    static_assert(BK % KSL == 0, "");
    static_assert(TN % 2 == 0, "");

    __shared__ __align__(16) float sA[BK][2*BM + 4];
    __shared__ __align__(16) float sB[BK][BN + 4];

    const int tid = threadIdx.x;
    const int m0  = blockIdx.x * BM;
    const int n0  = blockIdx.y * BN;

    const int a_k0 = (NT > BM) ? (tid / BM) : 0;
    const float* Abase[ROWS];
    int oh_[ROWS], aml[ROWS];
    const int IHW = IH * IW;
    if constexpr (!FLAT) {
#pragma unroll
        for (int r = 0; r < ROWS; r++) {
            const int ml = (NT >= BM) ? (tid % BM) : (tid + r * NT);
            aml[r] = ml;
            const int m = m0 + ml;
            const int b = m / SP;
            const int s = m - b * SP;
            if (MODE == 0) {
                const int oh = s / OW;
                oh_[r] = oh;
                Abase[r] = A + (long long)b * abstride + (s - oh * OW);
            } else {
                oh_[r] = 0;
                Abase[r] = A + (long long)b * abstride + (long long)s * K;
            }
        }
    }

    const int tn = tid % (BN/TN);
    const int tm = tid / (BN/TN);

    float2 acc[TM][TN/2];
#pragma unroll
    for (int i = 0; i < TM; i++)
#pragma unroll
        for (int j = 0; j < TN/2; j++) acc[i][j] = make_float2(0.f, 0.f);

    for (int kt = 0; kt < KITER; kt++) {
        const int k0 = kt * BK;
        if constexpr (FLAT) {
            const float* Ablk = A + (long long)m0 * K;
#pragma unroll
            for (int i4 = tid * 4; i4 < BM * K; i4 += NT * 4) {
                const float4 v = *(const float4*)(Ablk + i4);
#pragma unroll
                for (int e = 0; e < 4; e++) {
                    const int idx = i4 + e;
                    const int m = idx / K;
                    const int k = idx - m * K;
                    const float val = (&v.x)[e];
                    *(float2*)&sA[k][2*m] = make_float2(val, val);
                }
            }
        } else {
#pragma unroll
            for (int r = 0; r < ROWS; r++) {
#pragma unroll
                for (int j = 0; j < AJ; j++) {
                    const int kl = a_k0 + KSL * j;
                    const int k  = k0 + kl;
                    float v = 0.0f;
                    if (!KG || k < K) {
                        if (MODE == 0) {
                            const int ic = k / KH;
                            const int kh = k - ic * KH;
                            const int ih = oh_[r] + kh - PH;
                            if ((unsigned)ih < (unsigned)IH)
                                v = Abase[r][ic * IHW + ih * IW];
                        } else {
                            v = Abase[r][k];
                        }
                    }
                    *(float2*)&sA[kl][2 * aml[r]] = make_float2(v, v);
                }
            }
        }
        constexpr int BTOT = BK * BN;
        constexpr int BIT  = (BTOT + NT - 1) / NT;
#pragma unroll
        for (int t = 0; t < BIT; t++) {
            const int idx = tid + t * NT;
            if (BTOT % NT == 0 || idx < BTOT) {
                const int kl = idx % BK;
                const int n  = idx / BK;
                const int k  = k0 + kl;
                const int nn = n0 + n;
                float v = 0.0f;
                if ((!KG || k < K) && (!NG || nn < N)) v = W[nn * K + k];
                sB[kl][n] = v;
            }
        }
        __syncthreads();

#pragma unroll
        for (int kk = 0; kk < BK; kk++) {
            float2 a2[TM], b2[TN/2];
            {
                const float4* pa = (const float4*)&sA[kk][2 * tm * TM];
#pragma unroll
                for (int q = 0; q < TM/2; q++) {
                    const float4 t4 = pa[q];
                    a2[2*q]   = make_float2(t4.x, t4.y);
                    a2[2*q+1] = make_float2(t4.z, t4.w);
                }
            }
            if constexpr (TN % 4 == 0) {
                const float4* pb = (const float4*)&sB[kk][tn * TN];
#pragma unroll
                for (int q = 0; q < TN/4; q++) {
                    const float4 t4 = pb[q];
                    b2[2*q]   = make_float2(t4.x, t4.y);
                    b2[2*q+1] = make_float2(t4.z, t4.w);
                }
            } else {
                const float2* pb = (const float2*)&sB[kk][tn * TN];
#pragma unroll
                for (int q = 0; q < TN/2; q++) b2[q] = pb[q];
            }
#pragma unroll
            for (int i = 0; i < TM; i++)
#pragma unroll
                for (int j = 0; j < TN/2; j++)
                    ffma2(acc[i][j], a2[i], b2[j]);
        }
        __syncthreads();
    }

#pragma unroll
    for (int i = 0; i < TM; i++) {
        const int m = m0 + tm * TM + i;
        const int b = m / SP;
        const int s = m - b * SP;
#pragma unroll
        for (int j = 0; j < TN/2; j++) {
#pragma unroll
            for (int h = 0; h < 2; h++) {
                const int n = n0 + tn * TN + 2*j + h;
                if (!NG || n < N) {
                    float v = (h ? acc[i][j].y : acc[i][j].x) + bias[n];
                    if (RELU) v = fmaxf(v, 0.0f);
                    long long o;
                    if (MODE == 0) o = (long long)b * (N * SP) + (long long)n * SP + s;
                    else           o = (long long)b * (SP * N) + (long long)s * N + n;
                    if (ACCUM) v += Out[o];
                    if (FOUT) Out[o] = v;
                    if (HOUT) hOut[o] = split2(v);
                }
            }
        }
    }
}

// ============================================================================
// Tensor-core conv GEMM v3 (R11, proven best): pre-split half2, reg prefetch,
// double-buffered smem, tile 64x64x32, 128 threads.
// ============================================================================
__device__ __forceinline__ void mma16816(float* c, const uint32_t* a, const uint32_t* b) {
    asm volatile(
        "mma.sync.aligned.m16n8k16.row.col.f32.f16.f16.f32 "
        "{%0,%1,%2,%3}, {%4,%5,%6,%7}, {%8,%9}, {%0,%1,%2,%3};"
        : "+f"(c[0]), "+f"(c[1]), "+f"(c[2]), "+f"(c[3])
        : "r"(a[0]), "r"(a[1]), "r"(a[2]), "r"(a[3]), "r"(b[0]), "r"(b[1]));
}

template<int KH,int N,int K,int ACCUM,int HOUT,int NB>
__global__ void __launch_bounds__(128, 4)
tconv(const __half2* __restrict__ Ah, const __half2* __restrict__ Wh,
      const float* __restrict__ bias, float* __restrict__ Out, __half2* __restrict__ hOut,
      int IH, int IW, int PH, int SP, int OW, int abstride)
{
    constexpr int BM = 64, BN = 64, BK = 32;
    constexpr int KITER = (K + BK - 1) / BK;
    constexpr int PAD   = 38;
    __shared__ __align__(16) __half sAhi[2][BM][PAD];
    __shared__ __align__(16) __half sAlo[2][BM][PAD];
    __shared__ __align__(16) __half sBhi[2][BN][PAD];
    __shared__ __align__(16) __half sBlo[2][BN][PAD];

    const int tid  = threadIdx.x;
    const int nb   = (int)(blockIdx.x % NB);
    const int mb   = (int)(blockIdx.x / NB);
    const int m0   = mb * BM;
    const int n0   = nb * BN;
    const int IHW  = IH * IW;

    const int arow = tid & 63;
    const int ak0  = tid >> 6;
    const int am   = m0 + arow;
    const int ab   = am / SP;
    const int as   = am - ab * SP;
    const int aoh  = as / OW;
    const __half2* Abase = Ah + (long long)ab * abstride + (as - aoh * OW);

    const int bkl = tid & 31;
    const int bn0 = tid >> 5;

    const int warp = tid >> 5, lane = tid & 31;
    const int wm = (warp & 1) * 32;
    const int wn = (warp >> 1) * 32;
    const int gr = lane >> 2;
    const int gc = lane & 3;

    __half2 aR[16], bR[16];
    const __half2 Z2 = __float2half2_rn(0.0f);

    auto prefetch = [&](int kt) {
        const int k0 = kt * BK;
#pragma unroll
        for (int t = 0; t < 16; t++) {
            const int k = k0 + ak0 + 2 * t;
            __half2 v = Z2;
            if (K % BK == 0 || k < K) {
                const int ic = k / KH;
                const int kh = k - ic * KH;
                const int ih = aoh + kh - PH;
                if ((unsigned)ih < (unsigned)IH)
                    v = Abase[ic * IHW + ih * IW];
            }
            aR[t] = v;
        }
        const int kB = k0 + bkl;
#pragma unroll
        for (int t = 0; t < 16; t++) {
            const int nn = n0 + bn0 + 4 * t;
            __half2 v = Z2;
            if ((K % BK == 0 || kB < K) && (N % BN == 0 || nn < N))
                v = Wh[(long long)nn * K + kB];
            bR[t] = v;
        }
    };

    auto stage = [&](int p) {
#pragma unroll
        for (int t = 0; t < 16; t++) {
            const int kl = ak0 + 2 * t;
            sAhi[p][arow][kl] = __low2half(aR[t]);
            sAlo[p][arow][kl] = __high2half(aR[t]);
        }
#pragma unroll
        for (int t = 0; t < 16; t++) {
            const int nl = bn0 + 4 * t;
            sBhi[p][nl][bkl] = __low2half(bR[t]);
            sBlo[p][nl][bkl] = __high2half(bR[t]);
        }
    };

    float acc[2][4][4];
#pragma unroll
    for (int i = 0; i < 2; i++)
#pragma unroll
        for (int j = 0; j < 4; j++)
#pragma unroll
            for (int q = 0; q < 4; q++) acc[i][j][q] = 0.0f;

    auto compute = [&](int p) {
#pragma unroll
        for (int ck = 0; ck < BK / 16; ck++) {
            const int kb = ck * 16 + 2 * gc;
            uint32_t ahi[2][4], alo[2][4], bhi[4][2], blo[4][2];
#pragma unroll
            for (int ms = 0; ms < 2; ms++) {
                const int r0 = wm + ms * 16 + gr;
                ahi[ms][0] = *(const uint32_t*)&sAhi[p][r0    ][kb    ];
                ahi[ms][1] = *(const uint32_t*)&sAhi[p][r0 + 8][kb    ];
                ahi[ms][2] = *(const uint32_t*)&sAhi[p][r0    ][kb + 8];
                ahi[ms][3] = *(const uint32_t*)&sAhi[p][r0 + 8][kb + 8];
                alo[ms][0] = *(const uint32_t*)&sAlo[p][r0    ][kb    ];
                alo[ms][1] = *(const uint32_t*)&sAlo[p][r0 + 8][kb    ];
                alo[ms][2] = *(const uint32_t*)&sAlo[p][r0    ][kb + 8];
                alo[ms][3] = *(const uint32_t*)&sAlo[p][r0 + 8][kb + 8];
            }
#pragma unroll
            for (int ns = 0; ns < 4; ns++) {
                const int nr = wn + ns * 8 + gr;
                bhi[ns][0] = *(const uint32_t*)&sBhi[p][nr][kb    ];
                bhi[ns][1] = *(const uint32_t*)&sBhi[p][nr][kb + 8];
                blo[ns][0] = *(const uint32_t*)&sBlo[p][nr][kb    ];
                blo[ns][1] = *(const uint32_t*)&sBlo[p][nr][kb + 8];
            }
#pragma unroll
            for (int ms = 0; ms < 2; ms++)
#pragma unroll
                for (int ns = 0; ns < 4; ns++) {
                    mma16816(acc[ms][ns], ahi[ms], bhi[ns]);
                    mma16816(acc[ms][ns], ahi[ms], blo[ns]);
                    mma16816(acc[ms][ns], alo[ms], bhi[ns]);
                }
        }
    };

    prefetch(0);
    stage(0);
    __syncthreads();
    for (int kt = 0; kt < KITER; kt++) {
        if (kt + 1 < KITER) prefetch(kt + 1);
        compute(kt & 1);
        if (kt + 1 < KITER) {
            stage((kt + 1) & 1);
            __syncthreads();
        }
    }

#pragma unroll
    for (int ms = 0; ms < 2; ms++) {
        const int mr0 = m0 + wm + ms * 16 + gr;
#pragma unroll
        for (int half = 0; half < 2; half++) {
            const int m = mr0 + half * 8;
            const int b = m / SP;
            const int s = m - b * SP;
            const long long obase = (long long)b * (N * SP) + s;
#pragma unroll
            for (int ns = 0; ns < 4; ns++) {
                const int n = n0 + wn + ns * 8 + 2 * gc;
#pragma unroll
                for (int e = 0; e < 2; e++) {
                    const int nn = n + e;
                    if (N % BN == 0 || nn < N) {
                        float v = acc[ms][ns][half * 2 + e] + bias[nn];
                        const long long o = obase + (long long)nn * SP;
                        if (ACCUM) v += Out[o];
                        Out[o] = v;
                        if (HOUT) hOut[o] = split2(v);
                    }
                }
            }
        }
    }
}

// ---------------- host-side typed launchers ----------------
template<int KH,int N,int K,int ACCUM,int HOUT>
static void tconv_l(const __half2* A, const __half2* W, const float* b, float* O,
                    __half2* hO, int IH, int IW, int PH)
{
    constexpr int NB = (N + 63) / 64;
    const int OH = IH + 2*PH - KH + 1, OW = IW, SP = OH * OW;
    const long long M = (long long)BATCH * SP;
    dim3 g((unsigned)((M / 64) * NB));
    tconv<KH,N,K,ACCUM,HOUT,NB><<<g, 128>>>(A, W, b, O, hO, IH, IW, PH, SP, OW, (K/KH)*IH*IW);
}

template<int BN,int BK,int TM,int TN,int N,int K,int RELU,int HOUT,int FOUT>
static void sl(const float* A, const float* W, const float* b, float* O, __half2* hO, int SP)
{
    constexpr int BM = 128;
    const long long M = (long long)BATCH * SP;
    dim3 g((unsigned)(M / BM), (N + BN - 1) / BN);
    gemm<1,1,BM,BN,BK,TM,TN,N,K,RELU,0,HOUT,FOUT><<<g, (BM/TM)*(BN/TN)>>>(
        A, W, b, O, hO, 1, 1, 0, SP, 1, SP*K);
}

extern "C" void kernel_launch(void* const* d_in, const int* in_sizes, int n_in,
                              void* d_out, int out_size)
{
    (void)in_sizes; (void)n_in; (void)out_size;
    const float* x    = (const float*)d_in[0];
    const float* w0a  = (const float*)d_in[1];  const float* b0a  = (const float*)d_in[2];
    const float* wl0  = (const float*)d_in[3];  const float* bl0  = (const float*)d_in[4];
    const float* w0b  = (const float*)d_in[5];  const float* b0b  = (const float*)d_in[6];
    const float* w0c  = (const float*)d_in[7];  const float* b0c  = (const float*)d_in[8];
    const float* wr0  = (const float*)d_in[9];  const float* br0  = (const float*)d_in[10];
    const float* w1   = (const float*)d_in[11]; const float* b1   = (const float*)d_in[12];
    const float* wl1  = (const float*)d_in[13]; const float* bl1  = (const float*)d_in[14];
    const float* w2   = (const float*)d_in[15]; const float* b2   = (const float*)d_in[16];
    const float* wa   = (const float*)d_in[17]; const float* ba   = (const float*)d_in[18];
    const float* wra  = (const float*)d_in[19]; const float* bra  = (const float*)d_in[20];
    const float* w0   = (const float*)d_in[21]; const float* b0   = (const float*)d_in[22];
    const float* wl2  = (const float*)d_in[23]; const float* bl2  = (const float*)d_in[24];
    const float* w0b2 = (const float*)d_in[25]; const float* b0b2 = (const float*)d_in[26];
    const float* w0c2 = (const float*)d_in[27]; const float* b0c2 = (const float*)d_in[28];
    const float* wr02 = (const float*)d_in[29]; const float* br02 = (const float*)d_in[30];
    float* out = (float*)d_out;

    float *A, *Bb, *C, *x1, *x2;
    __half2 *hX, *hB, *hC, *hW;
    cudaGetSymbolAddress((void**)&A,  g_bufA);
    cudaGetSymbolAddress((void**)&Bb, g_bufB);
    cudaGetSymbolAddress((void**)&C,  g_bufC);
    cudaGetSymbolAddress((void**)&x1, g_x1);
    cudaGetSymbolAddress((void**)&x2, g_x2);
    cudaGetSymbolAddress((void**)&hX, g_hX);
    cudaGetSymbolAddress((void**)&hB, g_hB);
    cudaGetSymbolAddress((void**)&hC, g_hC);
    cudaGetSymbolAddress((void**)&hW, g_hW);

    __half2* hw1   = hW;            // 3750
    __half2* hw2   = hW + 3750;     // 18750
    __half2* hwa   = hW + 22500;    // 9375
    __half2* hw0   = hW + 31875;    // 75000
    __half2* hw0b2 = hW + 106875;   // 307200
    __half2* hw0c2 = hW + 414075;   // 192000
    split_w6<<<(606075 + 255) / 256, 256>>>(w1, w2, wa, w0, w0b2, w0c2, hW);

    // ---- stage 0: single fused kernel -> x1 + hX ----
    stage0_fused<<<BATCH / 4, 256>>>(x, w0a, b0a, wl0, bl0, w0b, b0b,
                                     w0c, b0c, wr0, br0, x1, hX);

    // ---- stage 1 ----
    tconv_l<2,  75,  50, 0,0>(hX, hw1, b1, A, nullptr, 5, 18, 0);
    sl<16,18, 4,4, 10,18, 1,1,0>(A,  wl1, bl1, Bb, hB, 300);   // relu, half only
    tconv_l<2, 125, 150, 0,0>(hB, hw2, b2, x2, nullptr, 4, 10, 0);
    sl<16,18, 4,4, 10,18, 0,1,0>(x1, wra, bra, C,  hC, 125);   // half only
    tconv_l<3, 125,  75, 1,1>(hC, hwa, ba, x2, hX, 5, 10, 0);  // += y, x2 + half

    // ---- stage 2 ----
    tconv_l<2, 300, 250, 0,0>(hX, hw0, b0, A, nullptr, 3, 10, 0);
    sl< 8,10, 4,2,  5,10, 1,1,0>(A,  wl2, bl2, Bb, hB, 600);   // relu, half only
    tconv_l<2, 512, 600, 0,0>(hB, hw0b2, b0b2, out, nullptr, 2, 5, 0);
    sl< 8,10, 4,2,  5,10, 0,1,0>(x2, wr02, br02, C,  hC, 375); // half only
    tconv_l<3, 512, 375, 1,0>(hC, hw0c2, b0c2, out, nullptr, 3, 5, 0);
}

// round 17
// speedup vs baseline: 1.9130x; 1.0977x over previous
#include <cuda_runtime.h>
#include <cuda_fp16.h>
#include <cstdint>

#define BATCH 16384

// ---------------- static scratch (device globals; no allocations) ----------------
__device__ float g_bufA[(long long)BATCH * 6000];
__device__ float g_bufB[(long long)BATCH * 3000];
__device__ float g_bufC[(long long)BATCH * 1875];
__device__ float g_x1 [(long long)BATCH * 2250];
__device__ float g_x2 [(long long)BATCH * 3750];
// half (hi,lo) interleaved planes for tensor-core consumers (activations)
__device__ __half2 g_hX[(long long)BATCH * 3750];
__device__ __half2 g_hB[(long long)BATCH * 3000];
__device__ __half2 g_hC[(long long)BATCH * 1875];
// prebuilt B tile images: per (n-block, k-tile): [hi 64x32 | lo 64x32] halves
__device__ __align__(16) __half g_bimg[1261568];

__device__ __forceinline__ __half2 split2(float v) {
    const __half hi = __float2half_rn(v);
    return __halves2half2(hi, __float2half_rn(v - __half2float(hi)));
}

__device__ __forceinline__ void ffma2(float2& d, const float2& a, const float2& b) {
    unsigned long long& dd = reinterpret_cast<unsigned long long&>(d);
    const unsigned long long& aa = reinterpret_cast<const unsigned long long&>(a);
    const unsigned long long& bb = reinterpret_cast<const unsigned long long&>(b);
    asm("fma.rn.f32x2 %0, %1, %2, %0;" : "+l"(dd) : "l"(aa), "l"(bb));
}

// ---------------- B-tile image builder (weights -> smem-image layout) ---------
// image[blk][plane][r][kk], blk = nb*KT + kt, plane 0=hi 1=lo, 64x32 halves.
template<int N, int K>
__global__ void build_bimg(const float* __restrict__ W, __half* __restrict__ img) {
    constexpr int KT   = (K + 31) / 32;
    constexpr int NBLK = (N + 63) / 64;
    constexpr int TOT  = NBLK * KT * 4096;
    const int idx = blockIdx.x * 256 + threadIdx.x;
    if (idx >= TOT) return;
    const int blk   = idx >> 12;
    const int rem   = idx & 4095;
    const int plane = rem >> 11;
    const int r     = (rem & 2047) >> 5;
    const int kk    = rem & 31;
    const int nb    = blk / KT;
    const int kt    = blk - nb * KT;
    const int n     = nb * 64 + r;
    const int k     = kt * 32 + kk;
    float v = 0.0f;
    if (n < N && k < K) v = W[n * K + k];
    const __half hi = __float2half_rn(v);
    img[idx] = plane ? __float2half_rn(v - __half2float(hi)) : hi;
}

// ============================================================================
// Fused stage 0 (R11, proven)
// ============================================================================
__global__ void __launch_bounds__(256)
stage0_fused(const float* __restrict__ X,
             const float* __restrict__ w0a, const float* __restrict__ b0a,
             const float* __restrict__ wl0, const float* __restrict__ bl0,
             const float* __restrict__ w0b, const float* __restrict__ b0b,
             const float* __restrict__ w0c, const float* __restrict__ b0c,
             const float* __restrict__ wr0, const float* __restrict__ br0,
             float* __restrict__ x1, __half2* __restrict__ hX)
{
    constexpr int ITEMS = 4;
    constexpr int W0A = 0, B0A = 15, WL0 = 20, BL0 = 506, WR0 = 524, BR0 = 1010,
                  W0B = 1028, B0B = 1403, W0C = 1428, B0C = 1453, WTOT = 1478;
    constexpr int PITEM = 1352;
    __shared__ float sm[WTOT + ITEMS * PITEM];

    const int tid = threadIdx.x;
    const long long base = (long long)blockIdx.x * ITEMS;

    for (int i = tid; i < WTOT; i += 256) {
        float v;
        if      (i < B0A) v = w0a[i - W0A];
        else if (i < WL0) v = b0a[i - B0A];
        else if (i < BL0) v = wl0[i - WL0];
        else if (i < WR0) v = bl0[i - BL0];
        else if (i < BR0) v = wr0[i - WR0];
        else if (i < W0B) v = br0[i - BR0];
        else if (i < B0B) v = w0b[i - W0B];
        else if (i < W0C) v = b0b[i - B0B];
        else if (i < B0C) v = w0c[i - W0C];
        else              v = b0c[i - B0C];
        sm[i] = v;
    }
    for (int i = tid; i < ITEMS * 135; i += 256) {
        const int it = i / 135, j = i - it * 135;
        sm[WTOT + it * PITEM + j] = X[(base + it) * 135 + j];
    }
    __syncthreads();

    for (int i = tid; i < ITEMS * 675; i += 256) {
        const int it = i / 675, q = i - it * 675;
        const int oc = q / 135, hw = q - oc * 135;
        const int h = hw / 27, w = hw - h * 27;
        const float* xi = &sm[WTOT + it * PITEM];
        float v = sm[B0A + oc];
#pragma unroll
        for (int kh = 0; kh < 3; kh++) {
            const int ih = h + kh - 1;
            if ((unsigned)ih < 5u)
                v = fmaf(xi[ih * 27 + w], sm[W0A + oc * 3 + kh], v);
        }
        sm[WTOT + it * PITEM + 135 + q] = v;
    }
    __syncthreads();

    for (int i = tid; i < ITEMS * (450 + 90); i += 256) {
        if (i < ITEMS * 450) {
            const int it = i / 450, q = i - it * 450;
            const int rr = q / 18, o = q - rr * 18;
            const float* z0 = &sm[WTOT + it * PITEM + 135 + rr * 27];
            float v = sm[BL0 + o];
            const float* wl = &sm[WL0 + o * 27];
#pragma unroll
            for (int w = 0; w < 27; w++) v = fmaf(z0[w], wl[w], v);
            sm[WTOT + it * PITEM + 810 + rr * 18 + o] = fmaxf(v, 0.0f);
        } else {
            const int j = i - ITEMS * 450;
            const int it = j / 90, q = j - it * 90;
            const int h = q / 18, o = q - h * 18;
            const float* xi = &sm[WTOT + it * PITEM + h * 27];
            float v = sm[BR0 + o];
            const float* wr = &sm[WR0 + o * 27];
#pragma unroll
            for (int w = 0; w < 27; w++) v = fmaf(xi[w], wr[w], v);
            sm[WTOT + it * PITEM + 1261 + q] = v;
        }
    }
    __syncthreads();

    for (int i = tid; i < ITEMS * 2250; i += 256) {
        const int it = i / 2250, r = i - it * 2250;
        const int oc = r / 90, ho = r - oc * 90;
        const int h = ho / 18, o = ho - h * 18;
        const float* z1 = &sm[WTOT + it * PITEM + 810];
        float v = sm[B0B + oc];
#pragma unroll
        for (int ic = 0; ic < 5; ic++) {
#pragma unroll
            for (int kh = 0; kh < 3; kh++) {
                const int ih = h + kh - 1;
                if ((unsigned)ih < 5u)
                    v = fmaf(z1[(ic * 5 + ih) * 18 + o], sm[W0B + oc * 15 + ic * 3 + kh], v);
            }
        }
        const float y = sm[WTOT + it * PITEM + 1261 + h * 18 + o];
        v = fmaf(y, sm[W0C + oc], v) + sm[B0C + oc];
        const long long gidx = (base + it) * 2250 + r;
        x1[gidx] = v;
        hX[gidx] = split2(v);
    }
}

// ============================================================================
// SIMT fp32 GEMM, flat coalesced A staging (semi-linear layers; R14 cfg)
// ============================================================================
template<int MODE,int KH,int BM,int BN,int BK,int TM,int TN,int N,int K,int RELU,int ACCUM,int HOUT,int FOUT>
__global__ void __launch_bounds__((BM/TM)*(BN/TN), 4)
gemm(const float* __restrict__ A, const float* __restrict__ W,
     const float* __restrict__ bias, float* __restrict__ Out, __half2* __restrict__ hOut,
     int IH, int IW, int PH, int SP, int OW, int abstride)
{
    constexpr int NT    = (BM/TM)*(BN/TN);
    constexpr int KITER = (K + BK - 1) / BK;
    constexpr bool KG   = (K % BK) != 0;
    constexpr bool NG   = (N % BN) != 0;
    constexpr bool FLAT = (MODE == 1 && KITER == 1 && !KG);
    constexpr int ROWS  = (BM > NT) ? BM/NT : 1;
    constexpr int KSL   = (NT > BM) ? NT/BM : 1;
    constexpr int AJ    = BK / KSL;
    static_assert(BK % KSL == 0, "");
    static_assert(TN % 2 == 0, "");

    __shared__ __align__(16) float sA[BK][2*BM + 4];
    __shared__ __align__(16) float sB[BK][BN + 4];

    const int tid = threadIdx.x;
    const int m0  = blockIdx.x * BM;
    const int n0  = blockIdx.y * BN;

    const int a_k0 = (NT > BM) ? (tid / BM) : 0;
    const float* Abase[ROWS];
    int oh_[ROWS], aml[ROWS];
    const int IHW = IH * IW;
    if constexpr (!FLAT) {
#pragma unroll
        for (int r = 0; r < ROWS; r++) {
            const int ml = (NT >= BM) ? (tid % BM) : (tid + r * NT);
            aml[r] = ml;
            const int m = m0 + ml;
            const int b = m / SP;
            const int s = m - b * SP;
            if (MODE == 0) {
                const int oh = s / OW;
                oh_[r] = oh;
                Abase[r] = A + (long long)b * abstride + (s - oh * OW);
            } else {
                oh_[r] = 0;
                Abase[r] = A + (long long)b * abstride + (long long)s * K;
            }
        }
    }

    const int tn = tid % (BN/TN);
    const int tm = tid / (BN/TN);

    float2 acc[TM][TN/2];
#pragma unroll
    for (int i = 0; i < TM; i++)
#pragma unroll
        for (int j = 0; j < TN/2; j++) acc[i][j] = make_float2(0.f, 0.f);

    for (int kt = 0; kt < KITER; kt++) {
        const int k0 = kt * BK;
        if constexpr (FLAT) {
            const float* Ablk = A + (long long)m0 * K;
#pragma unroll
            for (int i4 = tid * 4; i4 < BM * K; i4 += NT * 4) {
                const float4 v = *(const float4*)(Ablk + i4);
#pragma unroll
                for (int e = 0; e < 4; e++) {
                    const int idx = i4 + e;
                    const int m = idx / K;
                    const int k = idx - m * K;
                    const float val = (&v.x)[e];
                    *(float2*)&sA[k][2*m] = make_float2(val, val);
                }
            }
        } else {
#pragma unroll
            for (int r = 0; r < ROWS; r++) {
#pragma unroll
                for (int j = 0; j < AJ; j++) {
                    const int kl = a_k0 + KSL * j;
                    const int k  = k0 + kl;
                    float v = 0.0f;
                    if (!KG || k < K) {
                        if (MODE == 0) {
                            const int ic = k / KH;
                            const int kh = k - ic * KH;
                            const int ih = oh_[r] + kh - PH;
                            if ((unsigned)ih < (unsigned)IH)
                                v = Abase[r][ic * IHW + ih * IW];
                        } else {
                            v = Abase[r][k];
                        }
                    }
                    *(float2*)&sA[kl][2 * aml[r]] = make_float2(v, v);
                }
            }
        }
        constexpr int BTOT = BK * BN;
        constexpr int BIT  = (BTOT + NT - 1) / NT;
#pragma unroll
        for (int t = 0; t < BIT; t++) {
            const int idx = tid + t * NT;
            if (BTOT % NT == 0 || idx < BTOT) {
                const int kl = idx % BK;
                const int n  = idx / BK;
                const int k  = k0 + kl;
                const int nn = n0 + n;
                float v = 0.0f;
                if ((!KG || k < K) && (!NG || nn < N)) v = W[nn * K + k];
                sB[kl][n] = v;
            }
        }
        __syncthreads();

#pragma unroll
        for (int kk = 0; kk < BK; kk++) {
            float2 a2[TM], b2[TN/2];
            {
                const float4* pa = (const float4*)&sA[kk][2 * tm * TM];
#pragma unroll
                for (int q = 0; q < TM/2; q++) {
                    const float4 t4 = pa[q];
                    a2[2*q]   = make_float2(t4.x, t4.y);
                    a2[2*q+1] = make_float2(t4.z, t4.w);
                }
            }
            if constexpr (TN % 4 == 0) {
                const float4* pb = (const float4*)&sB[kk][tn * TN];
#pragma unroll
                for (int q = 0; q < TN/4; q++) {
                    const float4 t4 = pb[q];
                    b2[2*q]   = make_float2(t4.x, t4.y);
                    b2[2*q+1] = make_float2(t4.z, t4.w);
                }
            } else {
                const float2* pb = (const float2*)&sB[kk][tn * TN];
#pragma unroll
                for (int q = 0; q < TN/2; q++) b2[q] = pb[q];
            }
#pragma unroll
            for (int i = 0; i < TM; i++)
#pragma unroll
                for (int j = 0; j < TN/2; j++)
                    ffma2(acc[i][j], a2[i], b2[j]);
        }
        __syncthreads();
    }

#pragma unroll
    for (int i = 0; i < TM; i++) {
        const int m = m0 + tm * TM + i;
        const int b = m / SP;
        const int s = m - b * SP;
#pragma unroll
        for (int j = 0; j < TN/2; j++) {
#pragma unroll
            for (int h = 0; h < 2; h++) {
                const int n = n0 + tn * TN + 2*j + h;
                if (!NG || n < N) {
                    float v = (h ? acc[i][j].y : acc[i][j].x) + bias[n];
                    if (RELU) v = fmaxf(v, 0.0f);
                    long long o;
                    if (MODE == 0) o = (long long)b * (N * SP) + (long long)n * SP + s;
                    else           o = (long long)b * (SP * N) + (long long)s * N + n;
                    if (ACCUM) v += Out[o];
                    if (FOUT) Out[o] = v;
                    if (HOUT) hOut[o] = split2(v);
                }
            }
        }
    }
}

// ============================================================================
// Tensor-core conv GEMM v6: R11 A-path/MMA/epilogue; B staged as vectorized
// uint4 copies from a prebuilt global tile image (dense hi/lo planes, PAD=40).
// Tile 64x64x32, 128 threads, double-buffered smem.
// ============================================================================
__device__ __forceinline__ void mma16816(float* c, const uint32_t* a, const uint32_t* b) {
    asm volatile(
        "mma.sync.aligned.m16n8k16.row.col.f32.f16.f16.f32 "
        "{%0,%1,%2,%3}, {%4,%5,%6,%7}, {%8,%9}, {%0,%1,%2,%3};"
        : "+f"(c[0]), "+f"(c[1]), "+f"(c[2]), "+f"(c[3])
        : "r"(a[0]), "r"(a[1]), "r"(a[2]), "r"(a[3]), "r"(b[0]), "r"(b[1]));
}

template<int KH,int N,int K,int ACCUM,int HOUT,int NB>
__global__ void __launch_bounds__(128, 4)
tconv(const __half2* __restrict__ Ah, const __half* __restrict__ Bimg,
      const float* __restrict__ bias, float* __restrict__ Out, __half2* __restrict__ hOut,
      int IH, int IW, int PH, int SP, int OW, int abstride)
{
    constexpr int BM = 64, BN = 64, BK = 32;
    constexpr int KITER = (K + BK - 1) / BK;
    constexpr int PADA = 38;           // A planes: scalar STS conflict-free
    constexpr int PADB = 40;           // B planes: 80B rows, 16B-aligned, ldmatrix-free distinct banks
    __shared__ __align__(16) __half sAhi[2][BM][PADA];
    __shared__ __align__(16) __half sAlo[2][BM][PADA];
    __shared__ __align__(16) __half sB[2][2][BN][PADB];   // [buf][plane hi/lo][row][k]

    const int tid  = threadIdx.x;
    const int nb   = (int)(blockIdx.x % NB);
    const int mb   = (int)(blockIdx.x / NB);
    const int m0   = mb * BM;
    const int n0   = nb * BN;
    const int IHW  = IH * IW;

    const int arow = tid & 63;
    const int ak0  = tid >> 6;
    const int am   = m0 + arow;
    const int ab   = am / SP;
    const int as   = am - ab * SP;
    const int aoh  = as / OW;
    const __half2* Abase = Ah + (long long)ab * abstride + (as - aoh * OW);

    // B image: per tile 512 uint4 (8KB); thread copies 4 of them
    const uint4* Bimg4 = (const uint4*)Bimg + (long long)nb * KITER * 512;

    const int warp = tid >> 5, lane = tid & 31;
    const int wm = (warp & 1) * 32;
    const int wn = (warp >> 1) * 32;
    const int gr = lane >> 2;
    const int gc = lane & 3;

    __half2 aR[16];
    uint4 bV[4];
    const __half2 Z2 = __float2half2_rn(0.0f);

    auto prefetch = [&](int kt) {
        const int k0 = kt * BK;
#pragma unroll
        for (int t = 0; t < 16; t++) {
            const int k = k0 + ak0 + 2 * t;
            __half2 v = Z2;
            if (K % BK == 0 || k < K) {
                const int ic = k / KH;
                const int kh = k - ic * KH;
                const int ih = aoh + kh - PH;
                if ((unsigned)ih < (unsigned)IH)
                    v = Abase[ic * IHW + ih * IW];
            }
            aR[t] = v;
        }
        const uint4* src = Bimg4 + kt * 512 + tid;
#pragma unroll
        for (int i = 0; i < 4; i++) bV[i] = src[i * 128];
    };

    auto stage = [&](int p) {
#pragma unroll
        for (int t = 0; t < 16; t++) {
            const int kl = ak0 + 2 * t;
            sAhi[p][arow][kl] = __low2half(aR[t]);
            sAlo[p][arow][kl] = __high2half(aR[t]);
        }
#pragma unroll
        for (int i = 0; i < 4; i++) {
            const int idx = tid + i * 128;           // 0..511
            const int plane = idx >> 8;              // 0=hi, 1=lo
            const int w = idx & 255;
            const int r = w >> 2;
            const int c = w & 3;
            *(uint4*)&sB[p][plane][r][c * 8] = bV[i];
        }
    };

    float acc[2][4][4];
#pragma unroll
    for (int i = 0; i < 2; i++)
#pragma unroll
        for (int j = 0; j < 4; j++)
#pragma unroll
            for (int q = 0; q < 4; q++) acc[i][j][q] = 0.0f;

    auto compute = [&](int p) {
#pragma unroll
        for (int ck = 0; ck < BK / 16; ck++) {
            const int kb = ck * 16 + 2 * gc;
            uint32_t ahi[2][4], alo[2][4], bhi[4][2], blo[4][2];
#pragma unroll
            for (int ms = 0; ms < 2; ms++) {
                const int r0 = wm + ms * 16 + gr;
                ahi[ms][0] = *(const uint32_t*)&sAhi[p][r0    ][kb    ];
                ahi[ms][1] = *(const uint32_t*)&sAhi[p][r0 + 8][kb    ];
                ahi[ms][2] = *(const uint32_t*)&sAhi[p][r0    ][kb + 8];
                ahi[ms][3] = *(const uint32_t*)&sAhi[p][r0 + 8][kb + 8];
                alo[ms][0] = *(const uint32_t*)&sAlo[p][r0    ][kb    ];
                alo[ms][1] = *(const uint32_t*)&sAlo[p][r0 + 8][kb    ];
                alo[ms][2] = *(const uint32_t*)&sAlo[p][r0    ][kb + 8];
                alo[ms][3] = *(const uint32_t*)&sAlo[p][r0 + 8][kb + 8];
            }
#pragma unroll
            for (int ns = 0; ns < 4; ns++) {
                const int nr = wn + ns * 8 + gr;
                bhi[ns][0] = *(const uint32_t*)&sB[p][0][nr][kb    ];
                bhi[ns][1] = *(const uint32_t*)&sB[p][0][nr][kb + 8];
                blo[ns][0] = *(const uint32_t*)&sB[p][1][nr][kb    ];
                blo[ns][1] = *(const uint32_t*)&sB[p][1][nr][kb + 8];
            }
#pragma unroll
            for (int ms = 0; ms < 2; ms++)
#pragma unroll
                for (int ns = 0; ns < 4; ns++) {
                    mma16816(acc[ms][ns], ahi[ms], bhi[ns]);
                    mma16816(acc[ms][ns], ahi[ms], blo[ns]);
                    mma16816(acc[ms][ns], alo[ms], bhi[ns]);
                }
        }
    };

    prefetch(0);
    stage(0);
    __syncthreads();
    for (int kt = 0; kt < KITER; kt++) {
        if (kt + 1 < KITER) prefetch(kt + 1);
        compute(kt & 1);
        if (kt + 1 < KITER) {
            stage((kt + 1) & 1);
            __syncthreads();
        }
    }

#pragma unroll
    for (int ms = 0; ms < 2; ms++) {
        const int mr0 = m0 + wm + ms * 16 + gr;
#pragma unroll
        for (int half = 0; half < 2; half++) {
            const int m = mr0 + half * 8;
            const int b = m / SP;
            const int s = m - b * SP;
            const long long obase = (long long)b * (N * SP) + s;
#pragma unroll
            for (int ns = 0; ns < 4; ns++) {
                const int n = n0 + wn + ns * 8 + 2 * gc;
#pragma unroll
                for (int e = 0; e < 2; e++) {
                    const int nn = n + e;
                    if (N % BN == 0 || nn < N) {
                        float v = acc[ms][ns][half * 2 + e] + bias[nn];
                        const long long o = obase + (long long)nn * SP;
                        if (ACCUM) v += Out[o];
                        Out[o] = v;
                        if (HOUT) hOut[o] = split2(v);
                    }
                }
            }
        }
    }
}

// ---------------- host-side typed launchers ----------------
template<int KH,int N,int K,int ACCUM,int HOUT>
static void tconv_l(const __half2* A, const __half* Bimg, const float* b, float* O,
                    __half2* hO, int IH, int IW, int PH)
{
    constexpr int NB = (N + 63) / 64;
    const int OH = IH + 2*PH - KH + 1, OW = IW, SP = OH * OW;
    const long long M = (long long)BATCH * SP;
    dim3 g((unsigned)((M / 64) * NB));
    tconv<KH,N,K,ACCUM,HOUT,NB><<<g, 128>>>(A, Bimg, b, O, hO, IH, IW, PH, SP, OW, (K/KH)*IH*IW);
}

template<int BN,int BK,int TM,int TN,int N,int K,int RELU,int HOUT,int FOUT>
static void sl(const float* A, const float* W, const float* b, float* O, __half2* hO, int SP)
{
    constexpr int BM = 128;
    const long long M = (long long)BATCH * SP;
    dim3 g((unsigned)(M / BM), (N + BN - 1) / BN);
    gemm<1,1,BM,BN,BK,TM,TN,N,K,RELU,0,HOUT,FOUT><<<g, (BM/TM)*(BN/TN)>>>(
        A, W, b, O, hO, 1, 1, 0, SP, 1, SP*K);
}

template<int N,int K>
static void bprep(const float* W, __half* img)
{
    constexpr int TOT = ((N + 63) / 64) * ((K + 31) / 32) * 4096;
    build_bimg<N,K><<<(TOT + 255) / 256, 256>>>(W, img);
}

extern "C" void kernel_launch(void* const* d_in, const int* in_sizes, int n_in,
                              void* d_out, int out_size)
{
    (void)in_sizes; (void)n_in; (void)out_size;
    const float* x    = (const float*)d_in[0];
    const float* w0a  = (const float*)d_in[1];  const float* b0a  = (const float*)d_in[2];
    const float* wl0  = (const float*)d_in[3];  const float* bl0  = (const float*)d_in[4];
    const float* w0b  = (const float*)d_in[5];  const float* b0b  = (const float*)d_in[6];
    const float* w0c  = (const float*)d_in[7];  const float* b0c  = (const float*)d_in[8];
    const float* wr0  = (const float*)d_in[9];  const float* br0  = (const float*)d_in[10];
    const float* w1   = (const float*)d_in[11]; const float* b1   = (const float*)d_in[12];
    const float* wl1  = (const float*)d_in[13]; const float* bl1  = (const float*)d_in[14];
    const float* w2   = (const float*)d_in[15]; const float* b2   = (const float*)d_in[16];
    const float* wa   = (const float*)d_in[17]; const float* ba   = (const float*)d_in[18];
    const float* wra  = (const float*)d_in[19]; const float* bra  = (const float*)d_in[20];
    const float* w0   = (const float*)d_in[21]; const float* b0   = (const float*)d_in[22];
    const float* wl2  = (const float*)d_in[23]; const float* bl2  = (const float*)d_in[24];
    const float* w0b2 = (const float*)d_in[25]; const float* b0b2 = (const float*)d_in[26];
    const float* w0c2 = (const float*)d_in[27]; const float* b0c2 = (const float*)d_in[28];
    const float* wr02 = (const float*)d_in[29]; const float* br02 = (const float*)d_in[30];
    float* out = (float*)d_out;

    float *A, *Bb, *C, *x1, *x2;
    __half2 *hX, *hB, *hC;
    __half *bimg;
    cudaGetSymbolAddress((void**)&A,    g_bufA);
    cudaGetSymbolAddress((void**)&Bb,   g_bufB);
    cudaGetSymbolAddress((void**)&C,    g_bufC);
    cudaGetSymbolAddress((void**)&x1,   g_x1);
    cudaGetSymbolAddress((void**)&x2,   g_x2);
    cudaGetSymbolAddress((void**)&hX,   g_hX);
    cudaGetSymbolAddress((void**)&hB,   g_hB);
    cudaGetSymbolAddress((void**)&hC,   g_hC);
    cudaGetSymbolAddress((void**)&bimg, g_bimg);

    // ---- B tile images (offsets in halves; blk = 4096 halves) ----
    // w1:   NB=2, KT=2  -> 16384
    // w2:   NB=2, KT=5  -> 40960
    // wa:   NB=2, KT=3  -> 24576
    // w0:   NB=5, KT=8  -> 163840
    // w0b2: NB=8, KT=19 -> 622592
    // w0c2: NB=8, KT=12 -> 393216   total 1261568
    __half* pw1   = bimg;
    __half* pw2   = bimg + 16384;
    __half* pwa   = bimg + 57344;
    __half* pw0   = bimg + 81920;
    __half* pwb2  = bimg + 245760;
    __half* pwc2  = bimg + 868352;
    bprep< 75,  50>(w1,   pw1);
    bprep<125, 150>(w2,   pw2);
    bprep<125,  75>(wa,   pwa);
    bprep<300, 250>(w0,   pw0);
    bprep<512, 600>(w0b2, pwb2);
    bprep<512, 375>(w0c2, pwc2);

    // ---- stage 0: single fused kernel -> x1 + hX ----
    stage0_fused<<<BATCH / 4, 256>>>(x, w0a, b0a, wl0, bl0, w0b, b0b,
                                     w0c, b0c, wr0, br0, x1, hX);

    // ---- stage 1 ----
    tconv_l<2,  75,  50, 0,0>(hX, pw1, b1, A, nullptr, 5, 18, 0);
    sl<16,18, 4,4, 10,18, 1,1,0>(A,  wl1, bl1, Bb, hB, 300);   // relu, half only
    tconv_l<2, 125, 150, 0,0>(hB, pw2, b2, x2, nullptr, 4, 10, 0);
    sl<16,18, 4,4, 10,18, 0,1,0>(x1, wra, bra, C,  hC, 125);   // half only
    tconv_l<3, 125,  75, 1,1>(hC, pwa, ba, x2, hX, 5, 10, 0);  // += y, x2 + half

    // ---- stage 2 ----
    tconv_l<2, 300, 250, 0,0>(hX, pw0, b0, A, nullptr, 3, 10, 0);
    sl< 8,10, 4,2,  5,10, 1,1,0>(A,  wl2, bl2, Bb, hB, 600);   // relu, half only
    tconv_l<2, 512, 600, 0,0>(hB, pwb2, b0b2, out, nullptr, 2, 5, 0);
    sl< 8,10, 4,2,  5,10, 0,1,0>(x2, wr02, br02, C,  hC, 375); // half only
    tconv_l<3, 512, 375, 1,0>(hC, pwc2, b0c2, out, nullptr, 3, 5, 0);
}